// round 2
// baseline (speedup 1.0000x reference)
#include <cuda_runtime.h>
#include <cstdint>
#include <math.h>

// Problem constants
#define NB   32
#define TLEN 512
#define DDIM 1024
#define CDIM 120
#define NROWS 96            // 3 branches * 32 batches
#define INV_SCALE 0.015625f // 1 / (2*sqrt(1024)) = 1/64

// ---------------- scratch (device globals; no allocation allowed) ----------
__device__ float g_xsum[NROWS * DDIM];
__device__ float g_nv[NROWS];
__device__ float g_u[NROWS * DDIM];
__device__ float g_ub[NROWS];
__device__ float g_v[NROWS * DDIM];
__device__ float g_s[NROWS * TLEN];
__device__ float g_attn[NROWS * TLEN];
__device__ float g_ph[NROWS * DDIM];
__device__ float g_pooled[NROWS * DDIM];

#define NEG_INF __int_as_float(0xff800000)

// ---------------- K0: zero the pooled-h accumulator ------------------------
__global__ void zero_ph_kernel(float* ph) {
    int i = blockIdx.x * blockDim.x + threadIdx.x;
    if (i < NROWS * DDIM) ph[i] = 0.0f;
}

// ---------------- K1: masked token-sum of x + valid count ------------------
// grid (32, 3), 256 threads. Each thread owns 4 d-columns (float4).
// Masks are int32 (metadata dtypes are float32/int32/bf16; JAX bool -> int32).
__global__ void sum_kernel(const float* __restrict__ x0, const float* __restrict__ x1,
                           const float* __restrict__ x2,
                           const int* __restrict__ m0,
                           const int* __restrict__ m1,
                           const int* __restrict__ m2,
                           float* __restrict__ xsum, float* __restrict__ nv) {
    int b = blockIdx.x, br = blockIdx.y;
    const float* X = (br == 0) ? x0 : (br == 1) ? x1 : x2;
    const int* M = ((br == 0) ? m0 : (br == 1) ? m1 : m2) + (size_t)b * TLEN;
    __shared__ int sm[TLEN];
    int tid = threadIdx.x;
    if (tid < TLEN / 4) ((int4*)sm)[tid] = ((const int4*)M)[tid];
    __syncthreads();

    const float* base = X + ((size_t)b * TLEN) * DDIM + tid * 4;
    float ax = 0.f, ay = 0.f, az = 0.f, aw = 0.f;
    int cnt = 0;
    for (int t = 0; t < TLEN; t++) {
        if (sm[t] == 0) {
            float4 v = *(const float4*)(base + (size_t)t * DDIM);
            ax += v.x; ay += v.y; az += v.z; aw += v.w;
            cnt++;
        }
    }
    int row = br * NB + b;
    float4 o; o.x = ax; o.y = ay; o.z = az; o.w = aw;
    *(float4*)&xsum[(size_t)row * DDIM + tid * 4] = o;
    if (tid == 0) nv[row] = (float)cnt;
}

// ---------------- small GEMM: (96 x 1024) @ (1024 x 1024) ------------------
// MODE 0: C = A@B + nv[row]*bias[col]
// MODE 1: C = A@B^T
// MODE 2: C = A@B + bias[col]
template <int MODE>
__global__ void gemm96_kernel(const float* __restrict__ A, const float* __restrict__ B,
                              float* __restrict__ C, const float* __restrict__ bias,
                              const float* __restrict__ nv) {
    const int BM = 32, BN = 64, BK = 32;
    __shared__ float As[BM][BK + 1];
    __shared__ float Bs[BK][BN + 1];
    int m0 = blockIdx.y * BM;
    int n0 = blockIdx.x * BN;
    int tid = threadIdx.x;
    int tx = tid & 15, ty = tid >> 4;

    float acc[2][4] = {{0.f, 0.f, 0.f, 0.f}, {0.f, 0.f, 0.f, 0.f}};

    for (int k0 = 0; k0 < DDIM; k0 += BK) {
#pragma unroll
        for (int i = 0; i < 4; i++) {
            int l = tid + i * 256;
            int r = l >> 5, k = l & 31;
            As[r][k] = A[(size_t)(m0 + r) * DDIM + k0 + k];
        }
        if (MODE == 1) {
#pragma unroll
            for (int i = 0; i < 8; i++) {
                int l = tid + i * 256;
                int kk = l & 31, n = l >> 5;
                Bs[kk][n] = B[(size_t)(n0 + n) * DDIM + k0 + kk];
            }
        } else {
#pragma unroll
            for (int i = 0; i < 8; i++) {
                int l = tid + i * 256;
                int kk = l >> 6, n = l & 63;
                Bs[kk][n] = B[(size_t)(k0 + kk) * DDIM + n0 + n];
            }
        }
        __syncthreads();
#pragma unroll
        for (int kk = 0; kk < BK; kk++) {
            float a0 = As[ty * 2 + 0][kk];
            float a1 = As[ty * 2 + 1][kk];
#pragma unroll
            for (int j = 0; j < 4; j++) {
                float bv = Bs[kk][tx * 4 + j];
                acc[0][j] += a0 * bv;
                acc[1][j] += a1 * bv;
            }
        }
        __syncthreads();
    }
#pragma unroll
    for (int i = 0; i < 2; i++) {
        int r = m0 + ty * 2 + i;
#pragma unroll
        for (int j = 0; j < 4; j++) {
            int c = n0 + tx * 4 + j;
            float v = acc[i][j];
            if (MODE == 0) v += nv[r] * bias[c];
            if (MODE == 2) v += bias[c];
            C[(size_t)r * DDIM + c] = v;
        }
    }
}

// ---------------- K2c: ub[row] = u[row] . b_attn ----------------------------
__global__ void ub_kernel(const float* __restrict__ u, const float* __restrict__ ba,
                          float* __restrict__ ub) {
    int row = blockIdx.x;
    int tid = threadIdx.x;
    __shared__ float red[256];
    float p = 0.f;
    for (int d = tid; d < DDIM; d += 256) p += u[(size_t)row * DDIM + d] * ba[d];
    red[tid] = p;
    __syncthreads();
    for (int s = 128; s > 0; s >>= 1) {
        if (tid < s) red[tid] += red[tid + s];
        __syncthreads();
    }
    if (tid == 0) ub[row] = red[0];
}

// ---------------- K3: s[br,b,t] = (x_t . v + ub)/SCALE or -inf --------------
// grid (64, 32, 3), 256 threads (8 warps, one token per warp)
__global__ void s_kernel(const float* __restrict__ x0, const float* __restrict__ x1,
                         const float* __restrict__ x2,
                         const int* __restrict__ m0,
                         const int* __restrict__ m1,
                         const int* __restrict__ m2,
                         const float* __restrict__ v, const float* __restrict__ ub,
                         float* __restrict__ s) {
    int br = blockIdx.z, b = blockIdx.y;
    int w = threadIdx.x >> 5, lane = threadIdx.x & 31;
    int t = blockIdx.x * 8 + w;
    const float* X = (br == 0) ? x0 : (br == 1) ? x1 : x2;
    const int* M = (br == 0) ? m0 : (br == 1) ? m1 : m2;
    int row = br * NB + b;
    if (M[(size_t)b * TLEN + t] != 0) {
        if (lane == 0) s[(size_t)row * TLEN + t] = NEG_INF;
        return;
    }
    const float* xr = X + ((size_t)b * TLEN + t) * DDIM;
    const float* vr = v + (size_t)row * DDIM;
    float acc = 0.f;
#pragma unroll
    for (int i = 0; i < 8; i++) {
        int d = lane * 4 + i * 128;
        float4 xv = *(const float4*)&xr[d];
        float4 vv = *(const float4*)&vr[d];
        acc += xv.x * vv.x + xv.y * vv.y + xv.z * vv.z + xv.w * vv.w;
    }
#pragma unroll
    for (int o = 16; o > 0; o >>= 1) acc += __shfl_xor_sync(0xffffffffu, acc, o);
    if (lane == 0) s[(size_t)row * TLEN + t] = (acc + ub[row]) * INV_SCALE;
}

// ---------------- K4: softmax over T ----------------------------------------
// grid (32, 3), 256 threads, 2 tokens/thread
__global__ void softmax_kernel(const float* __restrict__ s, float* __restrict__ attn) {
    int row = blockIdx.y * NB + blockIdx.x;
    int tid = threadIdx.x;
    __shared__ float red[256];
    float v0 = s[(size_t)row * TLEN + tid];
    float v1 = s[(size_t)row * TLEN + tid + 256];
    red[tid] = fmaxf(v0, v1);
    __syncthreads();
    for (int st = 128; st > 0; st >>= 1) {
        if (tid < st) red[tid] = fmaxf(red[tid], red[tid + st]);
        __syncthreads();
    }
    float mx = red[0];
    __syncthreads();
    float e0 = expf(v0 - mx);
    float e1 = expf(v1 - mx);
    red[tid] = e0 + e1;
    __syncthreads();
    for (int st = 128; st > 0; st >>= 1) {
        if (tid < st) red[tid] += red[tid + st];
        __syncthreads();
    }
    float inv = 1.0f / red[0];
    attn[(size_t)row * TLEN + tid] = e0 * inv;
    attn[(size_t)row * TLEN + tid + 256] = e1 * inv;
}

// ---------------- K5: big GEMM h=relu(x@W1+b1) with fused attn pooling ------
// A virtual: 49152 x 1024 (three x tensors), B: W1 1024x1024.
// grid (8, 384), 256 threads, 128x128x16 tile, 8x8 per thread, f32x2 packed FMA.
__global__ __launch_bounds__(256, 2) void big_gemm_pool_kernel(
    const float* __restrict__ x0, const float* __restrict__ x1,
    const float* __restrict__ x2, const float* __restrict__ W1,
    const float* __restrict__ b1, const float* __restrict__ attn,
    float* __restrict__ ph) {
    __shared__ float As[16][128];
    __shared__ float Bs[16][128];
    __shared__ float colsum[128];

    int tid = threadIdx.x;
    int n0 = blockIdx.x * 128;
    int by = blockIdx.y;
    int branch = by >> 7;               // 128 row-blocks per branch
    int rloc = (by & 127) * 128;        // row within branch (token-major)
    const float* X = (branch == 0) ? x0 : (branch == 1) ? x1 : x2;

    int tx = tid & 15, ty = tid >> 4;

    unsigned long long acc[8][4];
#pragma unroll
    for (int r = 0; r < 8; r++)
#pragma unroll
        for (int p = 0; p < 4; p++) acc[r][p] = 0ull;

    float4 ra[2], rb[2];
    // prefetch k-step 0
#pragma unroll
    for (int i = 0; i < 2; i++) {
        int l = tid + i * 256;
        int m = l >> 2, kq = l & 3;
        ra[i] = *(const float4*)&X[(size_t)(rloc + m) * DDIM + kq * 4];
        int kk = l >> 5, n4 = l & 31;
        rb[i] = *(const float4*)&W1[(size_t)kk * DDIM + n0 + n4 * 4];
    }

    for (int ks = 0; ks < 64; ks++) {
        // commit staged tile to smem
#pragma unroll
        for (int i = 0; i < 2; i++) {
            int l = tid + i * 256;
            int m = l >> 2, kq = l & 3;
            As[kq * 4 + 0][m] = ra[i].x;
            As[kq * 4 + 1][m] = ra[i].y;
            As[kq * 4 + 2][m] = ra[i].z;
            As[kq * 4 + 3][m] = ra[i].w;
            int kk = l >> 5, n4 = l & 31;
            *(float4*)&Bs[kk][n4 * 4] = rb[i];
        }
        __syncthreads();
        if (ks < 63) {
            int k0 = (ks + 1) * 16;
#pragma unroll
            for (int i = 0; i < 2; i++) {
                int l = tid + i * 256;
                int m = l >> 2, kq = l & 3;
                ra[i] = *(const float4*)&X[(size_t)(rloc + m) * DDIM + k0 + kq * 4];
                int kk = l >> 5, n4 = l & 31;
                rb[i] = *(const float4*)&W1[(size_t)(k0 + kk) * DDIM + n0 + n4 * 4];
            }
        }
#pragma unroll
        for (int kk = 0; kk < 16; kk++) {
            float4 a0 = *(const float4*)&As[kk][ty * 4];
            float4 a1 = *(const float4*)&As[kk][ty * 4 + 64];
            unsigned long long b0 = *(const unsigned long long*)&Bs[kk][tx * 4];
            unsigned long long b1p = *(const unsigned long long*)&Bs[kk][tx * 4 + 2];
            unsigned long long b2 = *(const unsigned long long*)&Bs[kk][tx * 4 + 64];
            unsigned long long b3 = *(const unsigned long long*)&Bs[kk][tx * 4 + 66];
            float av[8] = {a0.x, a0.y, a0.z, a0.w, a1.x, a1.y, a1.z, a1.w};
#pragma unroll
            for (int r = 0; r < 8; r++) {
                unsigned long long aa;
                asm("mov.b64 %0, {%1, %1};" : "=l"(aa) : "f"(av[r]));
                asm("fma.rn.f32x2 %0, %1, %2, %0;" : "+l"(acc[r][0]) : "l"(aa), "l"(b0));
                asm("fma.rn.f32x2 %0, %1, %2, %0;" : "+l"(acc[r][1]) : "l"(aa), "l"(b1p));
                asm("fma.rn.f32x2 %0, %1, %2, %0;" : "+l"(acc[r][2]) : "l"(aa), "l"(b2));
                asm("fma.rn.f32x2 %0, %1, %2, %0;" : "+l"(acc[r][3]) : "l"(aa), "l"(b3));
            }
        }
        __syncthreads();
    }

    // ---- epilogue: relu(h + b1), weighted column sums, atomic into ph ----
    int bidx = (by & 127) >> 2;          // batch within branch (4 blocks of 128 per 512)
    int t0 = ((by & 127) & 3) * 128;
    int arow = branch * NB + bidx;
    const float* attnrow = attn + (size_t)arow * TLEN + t0;

    if (tid < 128) colsum[tid] = 0.f;
    __syncthreads();

    float bb[8], at[8];
#pragma unroll
    for (int j = 0; j < 8; j++) {
        int c = (j < 4) ? (tx * 4 + j) : (64 + tx * 4 + (j - 4));
        bb[j] = b1[n0 + c];
    }
#pragma unroll
    for (int r = 0; r < 8; r++) {
        int rl = (r < 4) ? (ty * 4 + r) : (64 + ty * 4 + (r - 4));
        at[r] = attnrow[rl];
    }
    float cs[8] = {0.f, 0.f, 0.f, 0.f, 0.f, 0.f, 0.f, 0.f};
#pragma unroll
    for (int r = 0; r < 8; r++) {
        float a = at[r];
#pragma unroll
        for (int p = 0; p < 4; p++) {
            float2 v = *(float2*)&acc[r][p];
            int j0 = p * 2;
            float h0 = fmaxf(v.x + bb[j0], 0.f);
            float h1 = fmaxf(v.y + bb[j0 + 1], 0.f);
            cs[j0] += a * h0;
            cs[j0 + 1] += a * h1;
        }
    }
#pragma unroll
    for (int j = 0; j < 8; j++) {
        int c = (j < 4) ? (tx * 4 + j) : (64 + tx * 4 + (j - 4));
        atomicAdd(&colsum[c], cs[j]);
    }
    __syncthreads();
    if (tid < 128) atomicAdd(&ph[(size_t)arow * DDIM + n0 + tid], colsum[tid]);
}

// ---------------- K6: layernorm + relu + last linear -----------------------
// grid (32, 3), 128 threads
__global__ void final_kernel(const float* __restrict__ pooled,
                             const float* __restrict__ ln_g, const float* __restrict__ ln_b,
                             const float* __restrict__ W_last, const float* __restrict__ b_last,
                             float* __restrict__ out) {
    int row = blockIdx.y * NB + blockIdx.x;
    int tid = threadIdx.x;
    __shared__ float act[DDIM];
    __shared__ float red[128];

    float vals[8];
    float lsum = 0.f;
#pragma unroll
    for (int i = 0; i < 8; i++) {
        vals[i] = pooled[(size_t)row * DDIM + tid + i * 128];
        lsum += vals[i];
    }
    red[tid] = lsum;
    __syncthreads();
    for (int s = 64; s > 0; s >>= 1) {
        if (tid < s) red[tid] += red[tid + s];
        __syncthreads();
    }
    float mu = red[0] * (1.0f / DDIM);
    __syncthreads();
    float lsq = 0.f;
#pragma unroll
    for (int i = 0; i < 8; i++) {
        float d = vals[i] - mu;
        lsq += d * d;
    }
    red[tid] = lsq;
    __syncthreads();
    for (int s = 64; s > 0; s >>= 1) {
        if (tid < s) red[tid] += red[tid + s];
        __syncthreads();
    }
    float var = red[0] * (1.0f / DDIM);
    float vv = var + 1e-12f;
    float inv = rsqrtf(vv);
    inv = inv * (1.5f - 0.5f * vv * inv * inv);  // Newton refine
    __syncthreads();
#pragma unroll
    for (int i = 0; i < 8; i++) {
        int d = tid + i * 128;
        float nvv = (vals[i] - mu) * inv * ln_g[d] + ln_b[d];
        act[d] = fmaxf(nvv, 0.f);
    }
    __syncthreads();
    if (tid < CDIM) {
        float accv = b_last[tid];
        for (int d = 0; d < DDIM; d++) accv += act[d] * W_last[(size_t)d * CDIM + tid];
        out[(size_t)row * CDIM + tid] = accv;
    }
}

// ---------------- launch ----------------------------------------------------
extern "C" void kernel_launch(void* const* d_in, const int* in_sizes, int n_in,
                              void* d_out, int out_size) {
    const float* x0 = (const float*)d_in[0];
    const float* x1 = (const float*)d_in[1];
    const float* x2 = (const float*)d_in[2];
    const int* m0 = (const int*)d_in[3];
    const int* m1 = (const int*)d_in[4];
    const int* m2 = (const int*)d_in[5];
    const float* W_attn = (const float*)d_in[6];
    const float* b_attn = (const float*)d_in[7];
    const float* W1 = (const float*)d_in[8];
    const float* b1 = (const float*)d_in[9];
    const float* W2 = (const float*)d_in[10];
    const float* b2 = (const float*)d_in[11];
    const float* ln_g = (const float*)d_in[12];
    const float* ln_b = (const float*)d_in[13];
    const float* W_last = (const float*)d_in[14];
    const float* b_last = (const float*)d_in[15];
    float* out = (float*)d_out;

    float *p_xsum, *p_nv, *p_u, *p_ub, *p_v, *p_s, *p_attn, *p_ph, *p_pooled;
    cudaGetSymbolAddress((void**)&p_xsum, g_xsum);
    cudaGetSymbolAddress((void**)&p_nv, g_nv);
    cudaGetSymbolAddress((void**)&p_u, g_u);
    cudaGetSymbolAddress((void**)&p_ub, g_ub);
    cudaGetSymbolAddress((void**)&p_v, g_v);
    cudaGetSymbolAddress((void**)&p_s, g_s);
    cudaGetSymbolAddress((void**)&p_attn, g_attn);
    cudaGetSymbolAddress((void**)&p_ph, g_ph);
    cudaGetSymbolAddress((void**)&p_pooled, g_pooled);

    zero_ph_kernel<<<NROWS, 1024>>>(p_ph);
    sum_kernel<<<dim3(NB, 3), 256>>>(x0, x1, x2, m0, m1, m2, p_xsum, p_nv);
    gemm96_kernel<0><<<dim3(16, 3), 256>>>(p_xsum, W_attn, p_u, b_attn, p_nv);
    ub_kernel<<<NROWS, 256>>>(p_u, b_attn, p_ub);
    gemm96_kernel<1><<<dim3(16, 3), 256>>>(p_u, W_attn, p_v, nullptr, nullptr);
    s_kernel<<<dim3(64, NB, 3), 256>>>(x0, x1, x2, m0, m1, m2, p_v, p_ub, p_s);
    softmax_kernel<<<dim3(NB, 3), 256>>>(p_s, p_attn);
    big_gemm_pool_kernel<<<dim3(8, 384), 256>>>(x0, x1, x2, W1, b1, p_attn, p_ph);
    gemm96_kernel<2><<<dim3(16, 3), 256>>>(p_ph, W2, p_pooled, b2, nullptr);
    final_kernel<<<dim3(NB, 3), 128>>>(p_pooled, ln_g, ln_b, W_last, b_last, out);
}

// round 4
// speedup vs baseline: 1.5797x; 1.5797x over previous
#include <cuda_runtime.h>
#include <cuda_bf16.h>
#include <cstdint>
#include <math.h>

// Problem constants
#define NB   32
#define TLEN 512
#define DDIM 1024
#define CDIM 120
#define NROWS 96            // 3 branches * 32 batches
#define INV_SCALE 0.015625f // 1 / (2*sqrt(1024)) = 1/64
#define TOTROWS 49152       // 3 * 32 * 512 tokens

#define NEG_INF __int_as_float(0xff800000)

// ---------------- scratch (device globals; no allocation allowed) ----------
__device__ float g_xsum[NROWS * DDIM];
__device__ float g_nv[NROWS];
__device__ float g_u[NROWS * DDIM];
__device__ float g_ub[NROWS];
__device__ float g_v[NROWS * DDIM];
__device__ float g_s[NROWS * TLEN];
__device__ float g_attn[NROWS * TLEN];
__device__ float g_ph[NROWS * DDIM];
__device__ float g_pooled[NROWS * DDIM];
// split-bf16 operands for the tensor-core GEMM
__device__ __nv_bfloat16 g_xhi[(size_t)TOTROWS * DDIM];
__device__ __nv_bfloat16 g_xlo[(size_t)TOTROWS * DDIM];
__device__ __nv_bfloat16 g_w1t_hi[DDIM * DDIM];
__device__ __nv_bfloat16 g_w1t_lo[DDIM * DDIM];

// =================== helpers =================================================
__device__ __forceinline__ void cp16(void* d, const void* s) {
    asm volatile("cp.async.cg.shared.global [%0], [%1], 16;"
                 :: "l"(__cvta_generic_to_shared(d)), "l"(s));
}
__device__ __forceinline__ void cp_commit() {
    asm volatile("cp.async.commit_group;" ::: "memory");
}
__device__ __forceinline__ void cp_wait1() {
    asm volatile("cp.async.wait_group 1;" ::: "memory");
}
__device__ __forceinline__ void mma_bf16(float* d, const uint32_t* a, const uint32_t* b) {
    asm volatile(
        "mma.sync.aligned.m16n8k16.row.col.f32.bf16.bf16.f32 "
        "{%0,%1,%2,%3}, {%4,%5,%6,%7}, {%8,%9}, {%0,%1,%2,%3};"
        : "+f"(d[0]), "+f"(d[1]), "+f"(d[2]), "+f"(d[3])
        : "r"(a[0]), "r"(a[1]), "r"(a[2]), "r"(a[3]), "r"(b[0]), "r"(b[1]));
}

// SMEM layout of big kernel: 3 stages x 40960B
// stage: Ahi[128][40] | Alo | Bhi[128][40] | Blo  (row stride 40 halfs = 80B)
#define STAGE_B   40960
#define PLANE_B   10240
#define ROW_B     80
#define OFF_ATT   122880
#define OFF_B1    123392
#define OFF_COL   123904
#define SMEM_REQ  124416

// ---------------- K0: zero the pooled-h accumulator ------------------------
__global__ void zero_ph_kernel(float* ph) {
    int i = blockIdx.x * blockDim.x + threadIdx.x;
    if (i < NROWS * DDIM) ph[i] = 0.0f;
}

// ---------------- conv: x -> bf16 hi/lo -------------------------------------
__global__ void conv_x_kernel(const float* __restrict__ x0, const float* __restrict__ x1,
                              const float* __restrict__ x2,
                              __nv_bfloat16* __restrict__ xhi,
                              __nv_bfloat16* __restrict__ xlo) {
    int br = blockIdx.y;
    const float* X = (br == 0) ? x0 : (br == 1) ? x1 : x2;
    size_t base = (size_t)br * (16384u * 1024u);
    size_t i = ((size_t)blockIdx.x * 256 + threadIdx.x) * 4;
    float4 v = *(const float4*)(X + i);
    __nv_bfloat16 h0 = __float2bfloat16(v.x);
    __nv_bfloat16 h1 = __float2bfloat16(v.y);
    __nv_bfloat16 h2 = __float2bfloat16(v.z);
    __nv_bfloat16 h3 = __float2bfloat16(v.w);
    __nv_bfloat16 l0 = __float2bfloat16(v.x - __bfloat162float(h0));
    __nv_bfloat16 l1 = __float2bfloat16(v.y - __bfloat162float(h1));
    __nv_bfloat16 l2 = __float2bfloat16(v.z - __bfloat162float(h2));
    __nv_bfloat16 l3 = __float2bfloat16(v.w - __bfloat162float(h3));
    __nv_bfloat162* ph = (__nv_bfloat162*)(xhi + base + i);
    __nv_bfloat162* pl = (__nv_bfloat162*)(xlo + base + i);
    ph[0] = __nv_bfloat162(h0, h1); ph[1] = __nv_bfloat162(h2, h3);
    pl[0] = __nv_bfloat162(l0, l1); pl[1] = __nv_bfloat162(l2, l3);
}

// ---------------- conv: W1 -> transposed bf16 hi/lo ------------------------
__global__ void conv_w1_kernel(const float* __restrict__ W1,
                               __nv_bfloat16* __restrict__ th,
                               __nv_bfloat16* __restrict__ tl) {
    __shared__ float tile[32][33];
    int n0 = blockIdx.x * 32, k0 = blockIdx.y * 32;
    int tx = threadIdx.x & 31, ty = threadIdx.x >> 5;
    for (int r = ty; r < 32; r += 8)
        tile[r][tx] = W1[(size_t)(k0 + r) * DDIM + n0 + tx];
    __syncthreads();
    for (int r = ty; r < 32; r += 8) {
        float v = tile[tx][r];  // = W1[k0+tx][n0+r]
        __nv_bfloat16 h = __float2bfloat16(v);
        __nv_bfloat16 l = __float2bfloat16(v - __bfloat162float(h));
        size_t o = (size_t)(n0 + r) * DDIM + k0 + tx;
        th[o] = h; tl[o] = l;
    }
}

// ---------------- K1: masked token-sum of x + valid count ------------------
__global__ void sum_kernel(const float* __restrict__ x0, const float* __restrict__ x1,
                           const float* __restrict__ x2,
                           const int* __restrict__ m0,
                           const int* __restrict__ m1,
                           const int* __restrict__ m2,
                           float* __restrict__ xsum, float* __restrict__ nv) {
    int b = blockIdx.x, br = blockIdx.y;
    const float* X = (br == 0) ? x0 : (br == 1) ? x1 : x2;
    const int* M = ((br == 0) ? m0 : (br == 1) ? m1 : m2) + (size_t)b * TLEN;
    __shared__ int sm[TLEN];
    int tid = threadIdx.x;
    if (tid < TLEN / 4) ((int4*)sm)[tid] = ((const int4*)M)[tid];
    __syncthreads();

    const float* base = X + ((size_t)b * TLEN) * DDIM + tid * 4;
    float ax = 0.f, ay = 0.f, az = 0.f, aw = 0.f;
    int cnt = 0;
    for (int t = 0; t < TLEN; t++) {
        if (sm[t] == 0) {
            float4 v = *(const float4*)(base + (size_t)t * DDIM);
            ax += v.x; ay += v.y; az += v.z; aw += v.w;
            cnt++;
        }
    }
    int row = br * NB + b;
    float4 o; o.x = ax; o.y = ay; o.z = az; o.w = aw;
    *(float4*)&xsum[(size_t)row * DDIM + tid * 4] = o;
    if (tid == 0) nv[row] = (float)cnt;
}

// ---------------- small GEMM: (96 x 1024) @ (1024 x 1024) ------------------
template <int MODE>
__global__ void gemm96_kernel(const float* __restrict__ A, const float* __restrict__ B,
                              float* __restrict__ C, const float* __restrict__ bias,
                              const float* __restrict__ nv) {
    const int BM = 32, BN = 64, BK = 32;
    __shared__ float As[BM][BK + 1];
    __shared__ float Bs[BK][BN + 1];
    int m0 = blockIdx.y * BM;
    int n0 = blockIdx.x * BN;
    int tid = threadIdx.x;
    int tx = tid & 15, ty = tid >> 4;

    float acc[2][4] = {{0.f, 0.f, 0.f, 0.f}, {0.f, 0.f, 0.f, 0.f}};

    for (int k0 = 0; k0 < DDIM; k0 += BK) {
#pragma unroll
        for (int i = 0; i < 4; i++) {
            int l = tid + i * 256;
            int r = l >> 5, k = l & 31;
            As[r][k] = A[(size_t)(m0 + r) * DDIM + k0 + k];
        }
        if (MODE == 1) {
#pragma unroll
            for (int i = 0; i < 8; i++) {
                int l = tid + i * 256;
                int kk = l & 31, n = l >> 5;
                Bs[kk][n] = B[(size_t)(n0 + n) * DDIM + k0 + kk];
            }
        } else {
#pragma unroll
            for (int i = 0; i < 8; i++) {
                int l = tid + i * 256;
                int kk = l >> 6, n = l & 63;
                Bs[kk][n] = B[(size_t)(k0 + kk) * DDIM + n0 + n];
            }
        }
        __syncthreads();
#pragma unroll
        for (int kk = 0; kk < BK; kk++) {
            float a0 = As[ty * 2 + 0][kk];
            float a1 = As[ty * 2 + 1][kk];
#pragma unroll
            for (int j = 0; j < 4; j++) {
                float bv = Bs[kk][tx * 4 + j];
                acc[0][j] += a0 * bv;
                acc[1][j] += a1 * bv;
            }
        }
        __syncthreads();
    }
#pragma unroll
    for (int i = 0; i < 2; i++) {
        int r = m0 + ty * 2 + i;
#pragma unroll
        for (int j = 0; j < 4; j++) {
            int c = n0 + tx * 4 + j;
            float v = acc[i][j];
            if (MODE == 0) v += nv[r] * bias[c];
            if (MODE == 2) v += bias[c];
            C[(size_t)r * DDIM + c] = v;
        }
    }
}

// ---------------- K2c: ub[row] = u[row] . b_attn ----------------------------
__global__ void ub_kernel(const float* __restrict__ u, const float* __restrict__ ba,
                          float* __restrict__ ub) {
    int row = blockIdx.x;
    int tid = threadIdx.x;
    __shared__ float red[256];
    float p = 0.f;
    for (int d = tid; d < DDIM; d += 256) p += u[(size_t)row * DDIM + d] * ba[d];
    red[tid] = p;
    __syncthreads();
    for (int s = 128; s > 0; s >>= 1) {
        if (tid < s) red[tid] += red[tid + s];
        __syncthreads();
    }
    if (tid == 0) ub[row] = red[0];
}

// ---------------- K3: s[br,b,t] = (x_t . v + ub)/SCALE or -inf --------------
__global__ void s_kernel(const float* __restrict__ x0, const float* __restrict__ x1,
                         const float* __restrict__ x2,
                         const int* __restrict__ m0,
                         const int* __restrict__ m1,
                         const int* __restrict__ m2,
                         const float* __restrict__ v, const float* __restrict__ ub,
                         float* __restrict__ s) {
    int br = blockIdx.z, b = blockIdx.y;
    int w = threadIdx.x >> 5, lane = threadIdx.x & 31;
    int t = blockIdx.x * 8 + w;
    const float* X = (br == 0) ? x0 : (br == 1) ? x1 : x2;
    const int* M = (br == 0) ? m0 : (br == 1) ? m1 : m2;
    int row = br * NB + b;
    if (M[(size_t)b * TLEN + t] != 0) {
        if (lane == 0) s[(size_t)row * TLEN + t] = NEG_INF;
        return;
    }
    const float* xr = X + ((size_t)b * TLEN + t) * DDIM;
    const float* vr = v + (size_t)row * DDIM;
    float acc = 0.f;
#pragma unroll
    for (int i = 0; i < 8; i++) {
        int d = lane * 4 + i * 128;
        float4 xv = *(const float4*)&xr[d];
        float4 vv = *(const float4*)&vr[d];
        acc += xv.x * vv.x + xv.y * vv.y + xv.z * vv.z + xv.w * vv.w;
    }
#pragma unroll
    for (int o = 16; o > 0; o >>= 1) acc += __shfl_xor_sync(0xffffffffu, acc, o);
    if (lane == 0) s[(size_t)row * TLEN + t] = (acc + ub[row]) * INV_SCALE;
}

// ---------------- K4: softmax over T ----------------------------------------
__global__ void softmax_kernel(const float* __restrict__ s, float* __restrict__ attn) {
    int row = blockIdx.y * NB + blockIdx.x;
    int tid = threadIdx.x;
    __shared__ float red[256];
    float v0 = s[(size_t)row * TLEN + tid];
    float v1 = s[(size_t)row * TLEN + tid + 256];
    red[tid] = fmaxf(v0, v1);
    __syncthreads();
    for (int st = 128; st > 0; st >>= 1) {
        if (tid < st) red[tid] = fmaxf(red[tid], red[tid + st]);
        __syncthreads();
    }
    float mx = red[0];
    __syncthreads();
    float e0 = expf(v0 - mx);
    float e1 = expf(v1 - mx);
    red[tid] = e0 + e1;
    __syncthreads();
    for (int st = 128; st > 0; st >>= 1) {
        if (tid < st) red[tid] += red[tid + st];
        __syncthreads();
    }
    float inv = 1.0f / red[0];
    attn[(size_t)row * TLEN + tid] = e0 * inv;
    attn[(size_t)row * TLEN + tid + 256] = e1 * inv;
}

// ---------------- K5: split-bf16 mma.sync GEMM with fused attn pooling -----
// grid (8, 384): bx = N-block (128 cols), by = M-block (128 tokens).
// 8 warps in 2x4; warp tile 64x32; mma m16n8k16; 3 splits (hh, hl, lh).
__global__ __launch_bounds__(256, 1) void big_mma_kernel(
    const __nv_bfloat16* __restrict__ xhi, const __nv_bfloat16* __restrict__ xlo,
    const __nv_bfloat16* __restrict__ wth, const __nv_bfloat16* __restrict__ wtl,
    const float* __restrict__ b1, const float* __restrict__ attn,
    float* __restrict__ ph) {
    extern __shared__ __align__(16) char smc[];
    float* att_s = (float*)(smc + OFF_ATT);
    float* b1s   = (float*)(smc + OFF_B1);
    float* cols  = (float*)(smc + OFF_COL);

    int tid = threadIdx.x;
    int wid = tid >> 5, lane = tid & 31;
    int wm = wid >> 2, wn = wid & 3;
    int g = lane >> 2, tg = lane & 3;

    int n0 = blockIdx.x * 128;
    int by = blockIdx.y;
    int branch = by >> 7, w_in = by & 127;
    int batch = w_in >> 2, quarter = w_in & 3;
    int arow = branch * NB + batch;
    size_t rowbase = (size_t)by * 128;

    if (tid < 128) {
        att_s[tid] = attn[(size_t)arow * TLEN + quarter * 128 + tid];
        b1s[tid] = b1[n0 + tid];
        cols[tid] = 0.f;
    }

    float acc[4][4][4];
#pragma unroll
    for (int mi = 0; mi < 4; mi++)
#pragma unroll
        for (int ni = 0; ni < 4; ni++)
#pragma unroll
            for (int j = 0; j < 4; j++) acc[mi][ni][j] = 0.f;

    // ---- stage loader: K=32 per stage; A/B hi+lo planes, row stride 80B ----
    auto load_stage = [&](int s) {
        char* buf = smc + (s % 3) * STAGE_B;
        int k0 = s * 32;
#pragma unroll
        for (int c = tid; c < 512; c += 256) {
            int r = c >> 2, j = c & 3;
            int off = r * ROW_B + j * 16;
            size_t asrc = (rowbase + r) * DDIM + k0 + j * 8;
            size_t bsrc = (size_t)(n0 + r) * DDIM + k0 + j * 8;
            cp16(buf + off, xhi + asrc);
            cp16(buf + PLANE_B + off, xlo + asrc);
            cp16(buf + 2 * PLANE_B + off, wth + bsrc);
            cp16(buf + 3 * PLANE_B + off, wtl + bsrc);
        }
    };

    load_stage(0); cp_commit();
    load_stage(1); cp_commit();

    int r0 = wm * 64 + g;
    int nr0 = wn * 32 + g;

    for (int s = 0; s < 32; ++s) {
        cp_wait1();
        __syncthreads();
        if (s + 2 < 32) { load_stage(s + 2); cp_commit(); }
        const char* buf = smc + (s % 3) * STAGE_B;
        const char* Ah = buf;
        const char* Al = buf + PLANE_B;
        const char* Bh = buf + 2 * PLANE_B;
        const char* Bl = buf + 3 * PLANE_B;
#pragma unroll
        for (int ksub = 0; ksub < 2; ++ksub) {
            int kb = (ksub * 16 + tg * 2) * 2;  // byte offset of k within row
            uint32_t ah[4][4], al[4][4], bh[4][2], bl[4][2];
#pragma unroll
            for (int mi = 0; mi < 4; mi++) {
                int rb = (r0 + mi * 16) * ROW_B + kb;
                ah[mi][0] = *(const uint32_t*)(Ah + rb);
                ah[mi][1] = *(const uint32_t*)(Ah + rb + 8 * ROW_B);
                ah[mi][2] = *(const uint32_t*)(Ah + rb + 16);
                ah[mi][3] = *(const uint32_t*)(Ah + rb + 8 * ROW_B + 16);
                al[mi][0] = *(const uint32_t*)(Al + rb);
                al[mi][1] = *(const uint32_t*)(Al + rb + 8 * ROW_B);
                al[mi][2] = *(const uint32_t*)(Al + rb + 16);
                al[mi][3] = *(const uint32_t*)(Al + rb + 8 * ROW_B + 16);
            }
#pragma unroll
            for (int ni = 0; ni < 4; ni++) {
                int nb = (nr0 + ni * 8) * ROW_B + kb;
                bh[ni][0] = *(const uint32_t*)(Bh + nb);
                bh[ni][1] = *(const uint32_t*)(Bh + nb + 16);
                bl[ni][0] = *(const uint32_t*)(Bl + nb);
                bl[ni][1] = *(const uint32_t*)(Bl + nb + 16);
            }
#pragma unroll
            for (int mi = 0; mi < 4; mi++)
#pragma unroll
                for (int ni = 0; ni < 4; ni++) {
                    mma_bf16(acc[mi][ni], ah[mi], bh[ni]);
                    mma_bf16(acc[mi][ni], ah[mi], bl[ni]);
                    mma_bf16(acc[mi][ni], al[mi], bh[ni]);
                }
        }
    }

    // ---- epilogue: pooled_col += sum_rows attn[row] * relu(acc + b1[col]) ----
    __syncthreads();
#pragma unroll
    for (int mi = 0; mi < 4; mi++) {
        int rA = wm * 64 + mi * 16 + g;
        float wA = att_s[rA], wB = att_s[rA + 8];
#pragma unroll
        for (int ni = 0; ni < 4; ni++) {
            int c0 = wn * 32 + ni * 8 + tg * 2;
            float bv0 = b1s[c0], bv1 = b1s[c0 + 1];
            float v0 = fmaxf(acc[mi][ni][0] + bv0, 0.f) * wA +
                       fmaxf(acc[mi][ni][2] + bv0, 0.f) * wB;
            float v1 = fmaxf(acc[mi][ni][1] + bv1, 0.f) * wA +
                       fmaxf(acc[mi][ni][3] + bv1, 0.f) * wB;
#pragma unroll
            for (int o = 4; o <= 16; o <<= 1) {
                v0 += __shfl_xor_sync(0xffffffffu, v0, o);
                v1 += __shfl_xor_sync(0xffffffffu, v1, o);
            }
            if (g == 0) {
                atomicAdd(&cols[c0], v0);
                atomicAdd(&cols[c0 + 1], v1);
            }
        }
    }
    __syncthreads();
    if (tid < 128) atomicAdd(&ph[(size_t)arow * DDIM + n0 + tid], cols[tid]);
}

// ---------------- K6: layernorm + relu + last linear -----------------------
__global__ void final_kernel(const float* __restrict__ pooled,
                             const float* __restrict__ ln_g, const float* __restrict__ ln_b,
                             const float* __restrict__ W_last, const float* __restrict__ b_last,
                             float* __restrict__ out) {
    int row = blockIdx.y * NB + blockIdx.x;
    int tid = threadIdx.x;
    __shared__ float act[DDIM];
    __shared__ float red[128];

    float vals[8];
    float lsum = 0.f;
#pragma unroll
    for (int i = 0; i < 8; i++) {
        vals[i] = pooled[(size_t)row * DDIM + tid + i * 128];
        lsum += vals[i];
    }
    red[tid] = lsum;
    __syncthreads();
    for (int s = 64; s > 0; s >>= 1) {
        if (tid < s) red[tid] += red[tid + s];
        __syncthreads();
    }
    float mu = red[0] * (1.0f / DDIM);
    __syncthreads();
    float lsq = 0.f;
#pragma unroll
    for (int i = 0; i < 8; i++) {
        float d = vals[i] - mu;
        lsq += d * d;
    }
    red[tid] = lsq;
    __syncthreads();
    for (int s = 64; s > 0; s >>= 1) {
        if (tid < s) red[tid] += red[tid + s];
        __syncthreads();
    }
    float var = red[0] * (1.0f / DDIM);
    float vv = var + 1e-12f;
    float inv = rsqrtf(vv);
    inv = inv * (1.5f - 0.5f * vv * inv * inv);  // Newton refine
    __syncthreads();
#pragma unroll
    for (int i = 0; i < 8; i++) {
        int d = tid + i * 128;
        float nvv = (vals[i] - mu) * inv * ln_g[d] + ln_b[d];
        act[d] = fmaxf(nvv, 0.f);
    }
    __syncthreads();
    if (tid < CDIM) {
        float accv = b_last[tid];
        for (int d = 0; d < DDIM; d++) accv += act[d] * W_last[(size_t)d * CDIM + tid];
        out[(size_t)row * CDIM + tid] = accv;
    }
}

// ---------------- launch ----------------------------------------------------
extern "C" void kernel_launch(void* const* d_in, const int* in_sizes, int n_in,
                              void* d_out, int out_size) {
    const float* x0 = (const float*)d_in[0];
    const float* x1 = (const float*)d_in[1];
    const float* x2 = (const float*)d_in[2];
    const int* m0 = (const int*)d_in[3];
    const int* m1 = (const int*)d_in[4];
    const int* m2 = (const int*)d_in[5];
    const float* W_attn = (const float*)d_in[6];
    const float* b_attn = (const float*)d_in[7];
    const float* W1 = (const float*)d_in[8];
    const float* b1 = (const float*)d_in[9];
    const float* W2 = (const float*)d_in[10];
    const float* b2 = (const float*)d_in[11];
    const float* ln_g = (const float*)d_in[12];
    const float* ln_b = (const float*)d_in[13];
    const float* W_last = (const float*)d_in[14];
    const float* b_last = (const float*)d_in[15];
    float* out = (float*)d_out;

    float *p_xsum, *p_nv, *p_u, *p_ub, *p_v, *p_s, *p_attn, *p_ph, *p_pooled;
    __nv_bfloat16 *p_xhi, *p_xlo, *p_wth, *p_wtl;
    cudaGetSymbolAddress((void**)&p_xsum, g_xsum);
    cudaGetSymbolAddress((void**)&p_nv, g_nv);
    cudaGetSymbolAddress((void**)&p_u, g_u);
    cudaGetSymbolAddress((void**)&p_ub, g_ub);
    cudaGetSymbolAddress((void**)&p_v, g_v);
    cudaGetSymbolAddress((void**)&p_s, g_s);
    cudaGetSymbolAddress((void**)&p_attn, g_attn);
    cudaGetSymbolAddress((void**)&p_ph, g_ph);
    cudaGetSymbolAddress((void**)&p_pooled, g_pooled);
    cudaGetSymbolAddress((void**)&p_xhi, g_xhi);
    cudaGetSymbolAddress((void**)&p_xlo, g_xlo);
    cudaGetSymbolAddress((void**)&p_wth, g_w1t_hi);
    cudaGetSymbolAddress((void**)&p_wtl, g_w1t_lo);

    cudaFuncSetAttribute(big_mma_kernel, cudaFuncAttributeMaxDynamicSharedMemorySize,
                         SMEM_REQ);

    zero_ph_kernel<<<NROWS, 1024>>>(p_ph);
    conv_x_kernel<<<dim3(16384, 3), 256>>>(x0, x1, x2, p_xhi, p_xlo);
    conv_w1_kernel<<<dim3(32, 32), 256>>>(W1, p_wth, p_wtl);
    sum_kernel<<<dim3(NB, 3), 256>>>(x0, x1, x2, m0, m1, m2, p_xsum, p_nv);
    gemm96_kernel<0><<<dim3(16, 3), 256>>>(p_xsum, W_attn, p_u, b_attn, p_nv);
    ub_kernel<<<NROWS, 256>>>(p_u, b_attn, p_ub);
    gemm96_kernel<1><<<dim3(16, 3), 256>>>(p_u, W_attn, p_v, nullptr, nullptr);
    s_kernel<<<dim3(64, NB, 3), 256>>>(x0, x1, x2, m0, m1, m2, p_v, p_ub, p_s);
    softmax_kernel<<<dim3(NB, 3), 256>>>(p_s, p_attn);
    big_mma_kernel<<<dim3(8, 384), 256, SMEM_REQ>>>(p_xhi, p_xlo, p_wth, p_wtl,
                                                    b1, p_attn, p_ph);
    gemm96_kernel<2><<<dim3(16, 3), 256>>>(p_ph, W2, p_pooled, b2, nullptr);
    final_kernel<<<dim3(NB, 3), 128>>>(p_pooled, ln_g, ln_b, W_last, b_last, out);
}

// round 5
// speedup vs baseline: 2.0009x; 1.2666x over previous
#include <cuda_runtime.h>
#include <cuda_bf16.h>
#include <cstdint>
#include <math.h>

// Problem constants
#define NB   32
#define TLEN 512
#define DDIM 1024
#define CDIM 120
#define NROWS 96            // 3 branches * 32 batches
#define INV_SCALE 0.015625f // 1 / (2*sqrt(1024)) = 1/64
#define TOTROWS 49152       // 3 * 32 * 512 tokens

#define NEG_INF __int_as_float(0xff800000)

// ---------------- scratch (device globals; no allocation allowed) ----------
__device__ float g_xsum[NROWS * DDIM];
__device__ float g_nv[NROWS];
__device__ float g_u[NROWS * DDIM];
__device__ float g_ub[NROWS];
__device__ float g_v[NROWS * DDIM];
__device__ float g_s[NROWS * TLEN];
__device__ float g_attn[NROWS * TLEN];
__device__ float g_ph[NROWS * DDIM];
__device__ float g_pooled[NROWS * DDIM];
// split-bf16 operands for the tensor-core GEMM
__device__ __nv_bfloat16 g_xhi[(size_t)TOTROWS * DDIM];
__device__ __nv_bfloat16 g_xlo[(size_t)TOTROWS * DDIM];
__device__ __nv_bfloat16 g_w1t_hi[DDIM * DDIM];
__device__ __nv_bfloat16 g_w1t_lo[DDIM * DDIM];

// =================== helpers =================================================
__device__ __forceinline__ void cp16(void* d, const void* s) {
    asm volatile("cp.async.cg.shared.global [%0], [%1], 16;"
                 :: "l"(__cvta_generic_to_shared(d)), "l"(s));
}
__device__ __forceinline__ void cp_commit() {
    asm volatile("cp.async.commit_group;" ::: "memory");
}
__device__ __forceinline__ void cp_wait1() {
    asm volatile("cp.async.wait_group 1;" ::: "memory");
}
__device__ __forceinline__ void cp_wait0() {
    asm volatile("cp.async.wait_group 0;" ::: "memory");
}
__device__ __forceinline__ void mma_bf16(float* d, const uint32_t* a, const uint32_t* b) {
    asm volatile(
        "mma.sync.aligned.m16n8k16.row.col.f32.bf16.bf16.f32 "
        "{%0,%1,%2,%3}, {%4,%5,%6,%7}, {%8,%9}, {%0,%1,%2,%3};"
        : "+f"(d[0]), "+f"(d[1]), "+f"(d[2]), "+f"(d[3])
        : "r"(a[0]), "r"(a[1]), "r"(a[2]), "r"(a[3]), "r"(b[0]), "r"(b[1]));
}
__device__ __forceinline__ void ldm4(uint32_t* r, uint32_t saddr) {
    asm volatile("ldmatrix.sync.aligned.m8n8.x4.shared.b16 {%0,%1,%2,%3}, [%4];"
                 : "=r"(r[0]), "=r"(r[1]), "=r"(r[2]), "=r"(r[3]) : "r"(saddr));
}

// SMEM layout of big kernel: 2 stages x 40960B
// stage: Ahi[128][40] | Alo | Bhi[128][40] | Blo  (row stride 40 halfs = 80B)
#define STAGE_B   40960
#define PLANE_B   10240
#define ROW_B     80
#define OFF_ATT   81920
#define OFF_B1    82432
#define OFF_COL   82944
#define SMEM_REQ  83456

// ---------------- K0: zero scratch accumulators -----------------------------
__global__ void zero_kernel(float* ph, float* xsum, float* nv) {
    int i = blockIdx.x * blockDim.x + threadIdx.x;
    if (i < NROWS * DDIM) { ph[i] = 0.0f; xsum[i] = 0.0f; }
    if (i < NROWS) nv[i] = 0.0f;
}

// ---------------- fused: x -> bf16 hi/lo + masked token-sum -----------------
// grid (8, 32, 3): 64 tokens per block; 256 threads, 4 cols each (float4).
__global__ void convsum_kernel(const float* __restrict__ x0, const float* __restrict__ x1,
                               const float* __restrict__ x2,
                               const int* __restrict__ m0,
                               const int* __restrict__ m1,
                               const int* __restrict__ m2,
                               __nv_bfloat16* __restrict__ xhi,
                               __nv_bfloat16* __restrict__ xlo,
                               float* __restrict__ xsum, float* __restrict__ nv) {
    int ch = blockIdx.x, b = blockIdx.y, br = blockIdx.z;
    const float* X = (br == 0) ? x0 : (br == 1) ? x1 : x2;
    const int* M = ((br == 0) ? m0 : (br == 1) ? m1 : m2) + (size_t)b * TLEN + ch * 64;
    __shared__ int sm[64];
    int tid = threadIdx.x;
    if (tid < 64) sm[tid] = M[tid];
    __syncthreads();

    size_t tokbase = (size_t)b * TLEN + ch * 64;
    size_t base = tokbase * DDIM + tid * 4;
    size_t brbase = (size_t)br * ((size_t)16384 * 1024);
    const float* xp = X + base;
    __nv_bfloat16* hp = xhi + brbase + base;
    __nv_bfloat16* lp = xlo + brbase + base;

    float ax = 0.f, ay = 0.f, az = 0.f, aw = 0.f;
    for (int t = 0; t < 64; t++) {
        float4 v = *(const float4*)(xp + (size_t)t * DDIM);
        __nv_bfloat16 h0 = __float2bfloat16(v.x);
        __nv_bfloat16 h1 = __float2bfloat16(v.y);
        __nv_bfloat16 h2 = __float2bfloat16(v.z);
        __nv_bfloat16 h3 = __float2bfloat16(v.w);
        __nv_bfloat16 l0 = __float2bfloat16(v.x - __bfloat162float(h0));
        __nv_bfloat16 l1 = __float2bfloat16(v.y - __bfloat162float(h1));
        __nv_bfloat16 l2 = __float2bfloat16(v.z - __bfloat162float(h2));
        __nv_bfloat16 l3 = __float2bfloat16(v.w - __bfloat162float(h3));
        __nv_bfloat162* ph2 = (__nv_bfloat162*)(hp + (size_t)t * DDIM);
        __nv_bfloat162* pl2 = (__nv_bfloat162*)(lp + (size_t)t * DDIM);
        ph2[0] = __nv_bfloat162(h0, h1); ph2[1] = __nv_bfloat162(h2, h3);
        pl2[0] = __nv_bfloat162(l0, l1); pl2[1] = __nv_bfloat162(l2, l3);
        if (sm[t] == 0) { ax += v.x; ay += v.y; az += v.z; aw += v.w; }
    }
    int row = br * NB + b;
    float* xr = xsum + (size_t)row * DDIM + tid * 4;
    atomicAdd(xr + 0, ax);
    atomicAdd(xr + 1, ay);
    atomicAdd(xr + 2, az);
    atomicAdd(xr + 3, aw);
    if (tid == 0) {
        int c = 0;
        for (int t = 0; t < 64; t++) c += (sm[t] == 0);
        atomicAdd(&nv[row], (float)c);
    }
}

// ---------------- conv: W1 -> transposed bf16 hi/lo ------------------------
__global__ void conv_w1_kernel(const float* __restrict__ W1,
                               __nv_bfloat16* __restrict__ th,
                               __nv_bfloat16* __restrict__ tl) {
    __shared__ float tile[32][33];
    int n0 = blockIdx.x * 32, k0 = blockIdx.y * 32;
    int tx = threadIdx.x & 31, ty = threadIdx.x >> 5;
    for (int r = ty; r < 32; r += 8)
        tile[r][tx] = W1[(size_t)(k0 + r) * DDIM + n0 + tx];
    __syncthreads();
    for (int r = ty; r < 32; r += 8) {
        float v = tile[tx][r];  // = W1[k0+tx][n0+r]
        __nv_bfloat16 h = __float2bfloat16(v);
        __nv_bfloat16 l = __float2bfloat16(v - __bfloat162float(h));
        size_t o = (size_t)(n0 + r) * DDIM + k0 + tx;
        th[o] = h; tl[o] = l;
    }
}

// ---------------- small GEMM: (96 x 1024) @ (1024 x 1024) ------------------
template <int MODE>
__global__ void gemm96_kernel(const float* __restrict__ A, const float* __restrict__ B,
                              float* __restrict__ C, const float* __restrict__ bias,
                              const float* __restrict__ nv) {
    const int BM = 32, BN = 64, BK = 32;
    __shared__ float As[BM][BK + 1];
    __shared__ float Bs[BK][BN + 1];
    int m0 = blockIdx.y * BM;
    int n0 = blockIdx.x * BN;
    int tid = threadIdx.x;
    int tx = tid & 15, ty = tid >> 4;

    float acc[2][4] = {{0.f, 0.f, 0.f, 0.f}, {0.f, 0.f, 0.f, 0.f}};

    for (int k0 = 0; k0 < DDIM; k0 += BK) {
#pragma unroll
        for (int i = 0; i < 4; i++) {
            int l = tid + i * 256;
            int r = l >> 5, k = l & 31;
            As[r][k] = A[(size_t)(m0 + r) * DDIM + k0 + k];
        }
        if (MODE == 1) {
#pragma unroll
            for (int i = 0; i < 8; i++) {
                int l = tid + i * 256;
                int kk = l & 31, n = l >> 5;
                Bs[kk][n] = B[(size_t)(n0 + n) * DDIM + k0 + kk];
            }
        } else {
#pragma unroll
            for (int i = 0; i < 8; i++) {
                int l = tid + i * 256;
                int kk = l >> 6, n = l & 63;
                Bs[kk][n] = B[(size_t)(k0 + kk) * DDIM + n0 + n];
            }
        }
        __syncthreads();
#pragma unroll
        for (int kk = 0; kk < BK; kk++) {
            float a0 = As[ty * 2 + 0][kk];
            float a1 = As[ty * 2 + 1][kk];
#pragma unroll
            for (int j = 0; j < 4; j++) {
                float bv = Bs[kk][tx * 4 + j];
                acc[0][j] += a0 * bv;
                acc[1][j] += a1 * bv;
            }
        }
        __syncthreads();
    }
#pragma unroll
    for (int i = 0; i < 2; i++) {
        int r = m0 + ty * 2 + i;
#pragma unroll
        for (int j = 0; j < 4; j++) {
            int c = n0 + tx * 4 + j;
            float v = acc[i][j];
            if (MODE == 0) v += nv[r] * bias[c];
            if (MODE == 2) v += bias[c];
            C[(size_t)r * DDIM + c] = v;
        }
    }
}

// ---------------- K2c: ub[row] = u[row] . b_attn ----------------------------
__global__ void ub_kernel(const float* __restrict__ u, const float* __restrict__ ba,
                          float* __restrict__ ub) {
    int row = blockIdx.x;
    int tid = threadIdx.x;
    __shared__ float red[256];
    float p = 0.f;
    for (int d = tid; d < DDIM; d += 256) p += u[(size_t)row * DDIM + d] * ba[d];
    red[tid] = p;
    __syncthreads();
    for (int s = 128; s > 0; s >>= 1) {
        if (tid < s) red[tid] += red[tid + s];
        __syncthreads();
    }
    if (tid == 0) ub[row] = red[0];
}

// ---------------- K3: s[br,b,t] = (x_t . v + ub)/SCALE or -inf --------------
__global__ void s_kernel(const float* __restrict__ x0, const float* __restrict__ x1,
                         const float* __restrict__ x2,
                         const int* __restrict__ m0,
                         const int* __restrict__ m1,
                         const int* __restrict__ m2,
                         const float* __restrict__ v, const float* __restrict__ ub,
                         float* __restrict__ s) {
    int br = blockIdx.z, b = blockIdx.y;
    int w = threadIdx.x >> 5, lane = threadIdx.x & 31;
    int t = blockIdx.x * 8 + w;
    const float* X = (br == 0) ? x0 : (br == 1) ? x1 : x2;
    const int* M = (br == 0) ? m0 : (br == 1) ? m1 : m2;
    int row = br * NB + b;
    if (M[(size_t)b * TLEN + t] != 0) {
        if (lane == 0) s[(size_t)row * TLEN + t] = NEG_INF;
        return;
    }
    const float* xr = X + ((size_t)b * TLEN + t) * DDIM;
    const float* vr = v + (size_t)row * DDIM;
    float acc = 0.f;
#pragma unroll
    for (int i = 0; i < 8; i++) {
        int d = lane * 4 + i * 128;
        float4 xv = *(const float4*)&xr[d];
        float4 vv = *(const float4*)&vr[d];
        acc += xv.x * vv.x + xv.y * vv.y + xv.z * vv.z + xv.w * vv.w;
    }
#pragma unroll
    for (int o = 16; o > 0; o >>= 1) acc += __shfl_xor_sync(0xffffffffu, acc, o);
    if (lane == 0) s[(size_t)row * TLEN + t] = (acc + ub[row]) * INV_SCALE;
}

// ---------------- K4: softmax over T ----------------------------------------
__global__ void softmax_kernel(const float* __restrict__ s, float* __restrict__ attn) {
    int row = blockIdx.y * NB + blockIdx.x;
    int tid = threadIdx.x;
    __shared__ float red[256];
    float v0 = s[(size_t)row * TLEN + tid];
    float v1 = s[(size_t)row * TLEN + tid + 256];
    red[tid] = fmaxf(v0, v1);
    __syncthreads();
    for (int st = 128; st > 0; st >>= 1) {
        if (tid < st) red[tid] = fmaxf(red[tid], red[tid + st]);
        __syncthreads();
    }
    float mx = red[0];
    __syncthreads();
    float e0 = expf(v0 - mx);
    float e1 = expf(v1 - mx);
    red[tid] = e0 + e1;
    __syncthreads();
    for (int st = 128; st > 0; st >>= 1) {
        if (tid < st) red[tid] += red[tid + st];
        __syncthreads();
    }
    float inv = 1.0f / red[0];
    attn[(size_t)row * TLEN + tid] = e0 * inv;
    attn[(size_t)row * TLEN + tid + 256] = e1 * inv;
}

// ---------------- K5: split-bf16 mma.sync GEMM with fused attn pooling -----
// grid (8, 384): bx = N-block (128 cols), by = M-block (128 tokens).
// 8 warps 2x4; warp tile 64x32; ldmatrix fragment loads; 2-stage cp.async; occ 2.
__global__ __launch_bounds__(256, 2) void big_mma_kernel(
    const __nv_bfloat16* __restrict__ xhi, const __nv_bfloat16* __restrict__ xlo,
    const __nv_bfloat16* __restrict__ wth, const __nv_bfloat16* __restrict__ wtl,
    const float* __restrict__ b1, const float* __restrict__ attn,
    float* __restrict__ ph) {
    extern __shared__ __align__(16) char smc[];
    float* att_s = (float*)(smc + OFF_ATT);
    float* b1s   = (float*)(smc + OFF_B1);
    float* cols  = (float*)(smc + OFF_COL);
    uint32_t sbase = (uint32_t)__cvta_generic_to_shared(smc);

    int tid = threadIdx.x;
    int wid = tid >> 5, lane = tid & 31;
    int wm = wid >> 2, wn = wid & 3;
    int g = lane >> 2, tg = lane & 3;

    int n0 = blockIdx.x * 128;
    int by = blockIdx.y;
    int branch = by >> 7, w_in = by & 127;
    int batch = w_in >> 2, quarter = w_in & 3;
    int arow = branch * NB + batch;
    size_t rowbase = (size_t)by * 128;

    if (tid < 128) {
        att_s[tid] = attn[(size_t)arow * TLEN + quarter * 128 + tid];
        b1s[tid] = b1[n0 + tid];
        cols[tid] = 0.f;
    }

    float acc[4][4][4];
#pragma unroll
    for (int mi = 0; mi < 4; mi++)
#pragma unroll
        for (int ni = 0; ni < 4; ni++)
#pragma unroll
            for (int j = 0; j < 4; j++) acc[mi][ni][j] = 0.f;

    // ---- stage loader: K=32 per stage; A/B hi+lo planes, row stride 80B ----
    auto load_stage = [&](int s) {
        char* buf = smc + (s & 1) * STAGE_B;
        int k0 = s * 32;
#pragma unroll
        for (int c = tid; c < 512; c += 256) {
            int r = c >> 2, j = c & 3;
            int off = r * ROW_B + j * 16;
            size_t asrc = (rowbase + r) * DDIM + k0 + j * 8;
            size_t bsrc = (size_t)(n0 + r) * DDIM + k0 + j * 8;
            cp16(buf + off, xhi + asrc);
            cp16(buf + PLANE_B + off, xlo + asrc);
            cp16(buf + 2 * PLANE_B + off, wth + bsrc);
            cp16(buf + 3 * PLANE_B + off, wtl + bsrc);
        }
    };

    // ldmatrix lane-address components
    uint32_t a_l = (uint32_t)((wm * 64 + (lane & 15)) * ROW_B + (lane >> 4) * 16);
    uint32_t b_l = (uint32_t)((wn * 32 + (lane & 7) + ((lane >> 4) << 3)) * ROW_B +
                              ((lane >> 3) & 1) * 16);

    load_stage(0); cp_commit();

    for (int s = 0; s < 32; ++s) {
        if (s + 1 < 32) { load_stage(s + 1); cp_commit(); cp_wait1(); }
        else            { cp_wait0(); }
        __syncthreads();
        uint32_t buf = sbase + (uint32_t)(s & 1) * STAGE_B;
#pragma unroll
        for (int ksub = 0; ksub < 2; ++ksub) {
            uint32_t aoff = buf + a_l + (uint32_t)ksub * 32u;
            uint32_t boff = buf + 2u * PLANE_B + b_l + (uint32_t)ksub * 32u;
            uint32_t a[4][4], bh[2][4], bl[2][4];
#pragma unroll
            for (int mi = 0; mi < 4; mi++) ldm4(a[mi], aoff + mi * (16 * ROW_B));
#pragma unroll
            for (int p = 0; p < 2; p++) {
                ldm4(bh[p], boff + p * (16 * ROW_B));
                ldm4(bl[p], boff + PLANE_B + p * (16 * ROW_B));
            }
#pragma unroll
            for (int mi = 0; mi < 4; mi++)
#pragma unroll
                for (int ni = 0; ni < 4; ni++) {
                    mma_bf16(acc[mi][ni], a[mi], &bh[ni >> 1][(ni & 1) * 2]);
                    mma_bf16(acc[mi][ni], a[mi], &bl[ni >> 1][(ni & 1) * 2]);
                }
            // lo-plane A reuses the a registers
#pragma unroll
            for (int mi = 0; mi < 4; mi++)
                ldm4(a[mi], aoff + PLANE_B + mi * (16 * ROW_B));
#pragma unroll
            for (int mi = 0; mi < 4; mi++)
#pragma unroll
                for (int ni = 0; ni < 4; ni++)
                    mma_bf16(acc[mi][ni], a[mi], &bh[ni >> 1][(ni & 1) * 2]);
        }
        __syncthreads();
    }

    // ---- epilogue: pooled_col += sum_rows attn[row] * relu(acc + b1[col]) ----
#pragma unroll
    for (int mi = 0; mi < 4; mi++) {
        int rA = wm * 64 + mi * 16 + g;
        float wA = att_s[rA], wB = att_s[rA + 8];
#pragma unroll
        for (int ni = 0; ni < 4; ni++) {
            int c0 = wn * 32 + ni * 8 + tg * 2;
            float bv0 = b1s[c0], bv1 = b1s[c0 + 1];
            float v0 = fmaxf(acc[mi][ni][0] + bv0, 0.f) * wA +
                       fmaxf(acc[mi][ni][2] + bv0, 0.f) * wB;
            float v1 = fmaxf(acc[mi][ni][1] + bv1, 0.f) * wA +
                       fmaxf(acc[mi][ni][3] + bv1, 0.f) * wB;
#pragma unroll
            for (int o = 4; o <= 16; o <<= 1) {
                v0 += __shfl_xor_sync(0xffffffffu, v0, o);
                v1 += __shfl_xor_sync(0xffffffffu, v1, o);
            }
            if (g == 0) {
                atomicAdd(&cols[c0], v0);
                atomicAdd(&cols[c0 + 1], v1);
            }
        }
    }
    __syncthreads();
    if (tid < 128) atomicAdd(&ph[(size_t)arow * DDIM + n0 + tid], cols[tid]);
}

// ---------------- K6: layernorm + relu + last linear -----------------------
__global__ void final_kernel(const float* __restrict__ pooled,
                             const float* __restrict__ ln_g, const float* __restrict__ ln_b,
                             const float* __restrict__ W_last, const float* __restrict__ b_last,
                             float* __restrict__ out) {
    int row = blockIdx.y * NB + blockIdx.x;
    int tid = threadIdx.x;
    __shared__ float act[DDIM];
    __shared__ float red[128];

    float vals[8];
    float lsum = 0.f;
#pragma unroll
    for (int i = 0; i < 8; i++) {
        vals[i] = pooled[(size_t)row * DDIM + tid + i * 128];
        lsum += vals[i];
    }
    red[tid] = lsum;
    __syncthreads();
    for (int s = 64; s > 0; s >>= 1) {
        if (tid < s) red[tid] += red[tid + s];
        __syncthreads();
    }
    float mu = red[0] * (1.0f / DDIM);
    __syncthreads();
    float lsq = 0.f;
#pragma unroll
    for (int i = 0; i < 8; i++) {
        float d = vals[i] - mu;
        lsq += d * d;
    }
    red[tid] = lsq;
    __syncthreads();
    for (int s = 64; s > 0; s >>= 1) {
        if (tid < s) red[tid] += red[tid + s];
        __syncthreads();
    }
    float var = red[0] * (1.0f / DDIM);
    float vv = var + 1e-12f;
    float inv = rsqrtf(vv);
    inv = inv * (1.5f - 0.5f * vv * inv * inv);  // Newton refine
    __syncthreads();
#pragma unroll
    for (int i = 0; i < 8; i++) {
        int d = tid + i * 128;
        float nvv = (vals[i] - mu) * inv * ln_g[d] + ln_b[d];
        act[d] = fmaxf(nvv, 0.f);
    }
    __syncthreads();
    if (tid < CDIM) {
        float accv = b_last[tid];
        for (int d = 0; d < DDIM; d++) accv += act[d] * W_last[(size_t)d * CDIM + tid];
        out[(size_t)row * CDIM + tid] = accv;
    }
}

// ---------------- launch ----------------------------------------------------
extern "C" void kernel_launch(void* const* d_in, const int* in_sizes, int n_in,
                              void* d_out, int out_size) {
    const float* x0 = (const float*)d_in[0];
    const float* x1 = (const float*)d_in[1];
    const float* x2 = (const float*)d_in[2];
    const int* m0 = (const int*)d_in[3];
    const int* m1 = (const int*)d_in[4];
    const int* m2 = (const int*)d_in[5];
    const float* W_attn = (const float*)d_in[6];
    const float* b_attn = (const float*)d_in[7];
    const float* W1 = (const float*)d_in[8];
    const float* b1 = (const float*)d_in[9];
    const float* W2 = (const float*)d_in[10];
    const float* b2 = (const float*)d_in[11];
    const float* ln_g = (const float*)d_in[12];
    const float* ln_b = (const float*)d_in[13];
    const float* W_last = (const float*)d_in[14];
    const float* b_last = (const float*)d_in[15];
    float* out = (float*)d_out;

    float *p_xsum, *p_nv, *p_u, *p_ub, *p_v, *p_s, *p_attn, *p_ph, *p_pooled;
    __nv_bfloat16 *p_xhi, *p_xlo, *p_wth, *p_wtl;
    cudaGetSymbolAddress((void**)&p_xsum, g_xsum);
    cudaGetSymbolAddress((void**)&p_nv, g_nv);
    cudaGetSymbolAddress((void**)&p_u, g_u);
    cudaGetSymbolAddress((void**)&p_ub, g_ub);
    cudaGetSymbolAddress((void**)&p_v, g_v);
    cudaGetSymbolAddress((void**)&p_s, g_s);
    cudaGetSymbolAddress((void**)&p_attn, g_attn);
    cudaGetSymbolAddress((void**)&p_ph, g_ph);
    cudaGetSymbolAddress((void**)&p_pooled, g_pooled);
    cudaGetSymbolAddress((void**)&p_xhi, g_xhi);
    cudaGetSymbolAddress((void**)&p_xlo, g_xlo);
    cudaGetSymbolAddress((void**)&p_wth, g_w1t_hi);
    cudaGetSymbolAddress((void**)&p_wtl, g_w1t_lo);

    cudaFuncSetAttribute(big_mma_kernel, cudaFuncAttributeMaxDynamicSharedMemorySize,
                         SMEM_REQ);

    zero_kernel<<<NROWS, 1024>>>(p_ph, p_xsum, p_nv);
    convsum_kernel<<<dim3(8, NB, 3), 256>>>(x0, x1, x2, m0, m1, m2,
                                            p_xhi, p_xlo, p_xsum, p_nv);
    conv_w1_kernel<<<dim3(32, 32), 256>>>(W1, p_wth, p_wtl);
    gemm96_kernel<0><<<dim3(16, 3), 256>>>(p_xsum, W_attn, p_u, b_attn, p_nv);
    ub_kernel<<<NROWS, 256>>>(p_u, b_attn, p_ub);
    gemm96_kernel<1><<<dim3(16, 3), 256>>>(p_u, W_attn, p_v, nullptr, nullptr);
    s_kernel<<<dim3(64, NB, 3), 256>>>(x0, x1, x2, m0, m1, m2, p_v, p_ub, p_s);
    softmax_kernel<<<dim3(NB, 3), 256>>>(p_s, p_attn);
    big_mma_kernel<<<dim3(8, 384), 256, SMEM_REQ>>>(p_xhi, p_xlo, p_wth, p_wtl,
                                                    b1, p_attn, p_ph);
    gemm96_kernel<2><<<dim3(16, 3), 256>>>(p_ph, W2, p_pooled, b2, nullptr);
    final_kernel<<<dim3(NB, 3), 128>>>(p_pooled, ln_g, ln_b, W_last, b_last, out);
}

// round 6
// speedup vs baseline: 2.1707x; 1.0849x over previous
#include <cuda_runtime.h>
#include <cuda_bf16.h>
#include <cstdint>
#include <math.h>

// Problem constants
#define NB   32
#define TLEN 512
#define DDIM 1024
#define CDIM 120
#define NROWS 96            // 3 branches * 32 batches
#define INV_SCALE 0.015625f // 1 / (2*sqrt(1024)) = 1/64
#define TOTROWS 49152       // 3 * 32 * 512 tokens

#define NEG_INF __int_as_float(0xff800000)

// ---------------- scratch (device globals; no allocation allowed) ----------
__device__ float g_xsum[NROWS * DDIM];
__device__ float g_nv[NROWS];
__device__ float g_u[NROWS * DDIM];
__device__ float g_ub[NROWS];
__device__ float g_v[NROWS * DDIM];
__device__ float g_s[NROWS * TLEN];
__device__ float g_ph[NROWS * DDIM];
__device__ float g_pooled[NROWS * DDIM];
// split-bf16 operands for the tensor-core GEMM
__device__ __nv_bfloat16 g_xhi[(size_t)TOTROWS * DDIM];
__device__ __nv_bfloat16 g_xlo[(size_t)TOTROWS * DDIM];
__device__ __nv_bfloat16 g_w1t_hi[DDIM * DDIM];
__device__ __nv_bfloat16 g_w1t_lo[DDIM * DDIM];

// =================== helpers =================================================
__device__ __forceinline__ void cp16(void* d, const void* s) {
    asm volatile("cp.async.cg.shared.global [%0], [%1], 16;"
                 :: "l"(__cvta_generic_to_shared(d)), "l"(s));
}
__device__ __forceinline__ void cp_commit() {
    asm volatile("cp.async.commit_group;" ::: "memory");
}
__device__ __forceinline__ void cp_wait0() {
    asm volatile("cp.async.wait_group 0;" ::: "memory");
}
__device__ __forceinline__ void mma_bf16(float* d, const uint32_t* a, const uint32_t* b) {
    asm volatile(
        "mma.sync.aligned.m16n8k16.row.col.f32.bf16.bf16.f32 "
        "{%0,%1,%2,%3}, {%4,%5,%6,%7}, {%8,%9}, {%0,%1,%2,%3};"
        : "+f"(d[0]), "+f"(d[1]), "+f"(d[2]), "+f"(d[3])
        : "r"(a[0]), "r"(a[1]), "r"(a[2]), "r"(a[3]), "r"(b[0]), "r"(b[1]));
}
__device__ __forceinline__ void ldm4(uint32_t* r, uint32_t saddr) {
    asm volatile("ldmatrix.sync.aligned.m8n8.x4.shared.b16 {%0,%1,%2,%3}, [%4];"
                 : "=r"(r[0]), "=r"(r[1]), "=r"(r[2]), "=r"(r[3]) : "r"(saddr));
}

// SMEM layout of big kernel: 2 stages x 61440B
// stage: Ahi[256][40] | Alo | Bhi[128][40] | Blo   (row stride 40 halfs = 80B)
#define ROW_B     80
#define PLANE_A   20480
#define PLANE_Bq  10240
#define STAGE_B   61440
#define OFF_ATT   122880   // 512 floats (softmax of full s row)
#define OFF_B1    124928   // 128 floats
#define OFF_COL   125440   // 128 floats
#define OFF_RED   125952   // 512 floats
#define SMEM_REQ  128000

// ---------------- K0: zero scratch + conv W1 (fused) ------------------------
// blocks [0,384): zero;  blocks [384,1408): W1 -> transposed bf16 hi/lo
__global__ void combo_kernel(const float* __restrict__ W1,
                             __nv_bfloat16* __restrict__ th,
                             __nv_bfloat16* __restrict__ tl,
                             float* __restrict__ ph, float* __restrict__ xsum,
                             float* __restrict__ u, float* __restrict__ v,
                             float* __restrict__ pooled,
                             float* __restrict__ nv, float* __restrict__ ub) {
    int bx = blockIdx.x;
    if (bx < 384) {
        int i = bx * 256 + threadIdx.x;   // covers 98304 = NROWS*DDIM
        ph[i] = 0.f; xsum[i] = 0.f; u[i] = 0.f; v[i] = 0.f; pooled[i] = 0.f;
        if (i < NROWS) { nv[i] = 0.f; ub[i] = 0.f; }
    } else {
        __shared__ float tile[32][33];
        int b = bx - 384;
        int n0 = (b & 31) * 32, k0 = (b >> 5) * 32;
        int tx = threadIdx.x & 31, ty = threadIdx.x >> 5;
        for (int r = ty; r < 32; r += 8)
            tile[r][tx] = W1[(size_t)(k0 + r) * DDIM + n0 + tx];
        __syncthreads();
        for (int r = ty; r < 32; r += 8) {
            float w = tile[tx][r];  // = W1[k0+tx][n0+r]
            __nv_bfloat16 h = __float2bfloat16(w);
            __nv_bfloat16 l = __float2bfloat16(w - __bfloat162float(h));
            size_t o = (size_t)(n0 + r) * DDIM + k0 + tx;
            th[o] = h; tl[o] = l;
        }
    }
}

// ---------------- fused: x -> bf16 hi/lo + masked token-sum -----------------
__global__ void convsum_kernel(const float* __restrict__ x0, const float* __restrict__ x1,
                               const float* __restrict__ x2,
                               const int* __restrict__ m0,
                               const int* __restrict__ m1,
                               const int* __restrict__ m2,
                               __nv_bfloat16* __restrict__ xhi,
                               __nv_bfloat16* __restrict__ xlo,
                               float* __restrict__ xsum, float* __restrict__ nv) {
    int ch = blockIdx.x, b = blockIdx.y, br = blockIdx.z;
    const float* X = (br == 0) ? x0 : (br == 1) ? x1 : x2;
    const int* M = ((br == 0) ? m0 : (br == 1) ? m1 : m2) + (size_t)b * TLEN + ch * 64;
    __shared__ int sm[64];
    int tid = threadIdx.x;
    if (tid < 64) sm[tid] = M[tid];
    __syncthreads();

    size_t tokbase = (size_t)b * TLEN + ch * 64;
    size_t base = tokbase * DDIM + tid * 4;
    size_t brbase = (size_t)br * ((size_t)16384 * 1024);
    const float* xp = X + base;
    __nv_bfloat16* hp = xhi + brbase + base;
    __nv_bfloat16* lp = xlo + brbase + base;

    float ax = 0.f, ay = 0.f, az = 0.f, aw = 0.f;
    for (int t = 0; t < 64; t++) {
        float4 v = *(const float4*)(xp + (size_t)t * DDIM);
        __nv_bfloat16 h0 = __float2bfloat16(v.x);
        __nv_bfloat16 h1 = __float2bfloat16(v.y);
        __nv_bfloat16 h2 = __float2bfloat16(v.z);
        __nv_bfloat16 h3 = __float2bfloat16(v.w);
        __nv_bfloat16 l0 = __float2bfloat16(v.x - __bfloat162float(h0));
        __nv_bfloat16 l1 = __float2bfloat16(v.y - __bfloat162float(h1));
        __nv_bfloat16 l2 = __float2bfloat16(v.z - __bfloat162float(h2));
        __nv_bfloat16 l3 = __float2bfloat16(v.w - __bfloat162float(h3));
        __nv_bfloat162* ph2 = (__nv_bfloat162*)(hp + (size_t)t * DDIM);
        __nv_bfloat162* pl2 = (__nv_bfloat162*)(lp + (size_t)t * DDIM);
        ph2[0] = __nv_bfloat162(h0, h1); ph2[1] = __nv_bfloat162(h2, h3);
        pl2[0] = __nv_bfloat162(l0, l1); pl2[1] = __nv_bfloat162(l2, l3);
        if (sm[t] == 0) { ax += v.x; ay += v.y; az += v.z; aw += v.w; }
    }
    int row = br * NB + b;
    float* xr = xsum + (size_t)row * DDIM + tid * 4;
    atomicAdd(xr + 0, ax);
    atomicAdd(xr + 1, ay);
    atomicAdd(xr + 2, az);
    atomicAdd(xr + 3, aw);
    if (tid == 0) {
        int c = 0;
        for (int t = 0; t < 64; t++) c += (sm[t] == 0);
        atomicAdd(&nv[row], (float)c);
    }
}

// ---------------- small GEMM, K-split x4: (96 x 1024) @ (1024 x 1024) -------
// MODE 0: C += A@B (+ nv*bias @z0), and ub[r] += sum_c C_partial[r][c]*bias[c]
// MODE 1: C += A@B^T
// MODE 2: C += A@B (+ bias @z0)
template <int MODE>
__global__ void gemm96_kernel(const float* __restrict__ A, const float* __restrict__ B,
                              float* __restrict__ C, const float* __restrict__ bias,
                              const float* __restrict__ nv, float* __restrict__ ub) {
    const int BK = 32;
    __shared__ float As[32][BK + 1];
    __shared__ float Bs[BK][64 + 1];
    int m0 = blockIdx.y * 32;
    int n0 = blockIdx.x * 64;
    int ks = blockIdx.z * 256;
    int tid = threadIdx.x;
    int tx = tid & 15, ty = tid >> 4;
    int lane = tid & 31;

    float acc[2][4] = {{0.f, 0.f, 0.f, 0.f}, {0.f, 0.f, 0.f, 0.f}};

    for (int k0 = ks; k0 < ks + 256; k0 += BK) {
#pragma unroll
        for (int i = 0; i < 4; i++) {
            int l = tid + i * 256;
            int r = l >> 5, k = l & 31;
            As[r][k] = A[(size_t)(m0 + r) * DDIM + k0 + k];
        }
        if (MODE == 1) {
#pragma unroll
            for (int i = 0; i < 8; i++) {
                int l = tid + i * 256;
                int kk = l & 31, n = l >> 5;
                Bs[kk][n] = B[(size_t)(n0 + n) * DDIM + k0 + kk];
            }
        } else {
#pragma unroll
            for (int i = 0; i < 8; i++) {
                int l = tid + i * 256;
                int kk = l >> 6, n = l & 63;
                Bs[kk][n] = B[(size_t)(k0 + kk) * DDIM + n0 + n];
            }
        }
        __syncthreads();
#pragma unroll
        for (int kk = 0; kk < BK; kk++) {
            float a0 = As[ty * 2 + 0][kk];
            float a1 = As[ty * 2 + 1][kk];
#pragma unroll
            for (int j = 0; j < 4; j++) {
                float bv = Bs[kk][tx * 4 + j];
                acc[0][j] += a0 * bv;
                acc[1][j] += a1 * bv;
            }
        }
        __syncthreads();
    }

    float vv[2][4];
#pragma unroll
    for (int i = 0; i < 2; i++) {
        int r = m0 + ty * 2 + i;
#pragma unroll
        for (int j = 0; j < 4; j++) {
            int c = n0 + tx * 4 + j;
            float v = acc[i][j];
            if (MODE == 0 && blockIdx.z == 0) v += nv[r] * bias[c];
            if (MODE == 2 && blockIdx.z == 0) v += bias[c];
            vv[i][j] = v;
            atomicAdd(&C[(size_t)r * DDIM + c], v);
        }
    }
    if (MODE == 0) {
        float u0 = 0.f, u1 = 0.f;
#pragma unroll
        for (int j = 0; j < 4; j++) {
            float ba = bias[n0 + tx * 4 + j];
            u0 += vv[0][j] * ba;
            u1 += vv[1][j] * ba;
        }
#pragma unroll
        for (int o = 8; o > 0; o >>= 1) {
            u0 += __shfl_xor_sync(0xffffffffu, u0, o);
            u1 += __shfl_xor_sync(0xffffffffu, u1, o);
        }
        if ((lane & 15) == 0) {
            atomicAdd(&ub[m0 + ty * 2 + 0], u0);
            atomicAdd(&ub[m0 + ty * 2 + 1], u1);
        }
    }
}

// ---------------- K3: s[br,b,t] = (x_t . v + ub)/SCALE or -inf --------------
__global__ void s_kernel(const float* __restrict__ x0, const float* __restrict__ x1,
                         const float* __restrict__ x2,
                         const int* __restrict__ m0,
                         const int* __restrict__ m1,
                         const int* __restrict__ m2,
                         const float* __restrict__ v, const float* __restrict__ ub,
                         float* __restrict__ s) {
    int br = blockIdx.z, b = blockIdx.y;
    int w = threadIdx.x >> 5, lane = threadIdx.x & 31;
    int t = blockIdx.x * 8 + w;
    const float* X = (br == 0) ? x0 : (br == 1) ? x1 : x2;
    const int* M = (br == 0) ? m0 : (br == 1) ? m1 : m2;
    int row = br * NB + b;
    if (M[(size_t)b * TLEN + t] != 0) {
        if (lane == 0) s[(size_t)row * TLEN + t] = NEG_INF;
        return;
    }
    const float* xr = X + ((size_t)b * TLEN + t) * DDIM;
    const float* vr = v + (size_t)row * DDIM;
    float acc = 0.f;
#pragma unroll
    for (int i = 0; i < 8; i++) {
        int d = lane * 4 + i * 128;
        float4 xv = *(const float4*)&xr[d];
        float4 vv = *(const float4*)&vr[d];
        acc += xv.x * vv.x + xv.y * vv.y + xv.z * vv.z + xv.w * vv.w;
    }
#pragma unroll
    for (int o = 16; o > 0; o >>= 1) acc += __shfl_xor_sync(0xffffffffu, acc, o);
    if (lane == 0) s[(size_t)row * TLEN + t] = (acc + ub[row]) * INV_SCALE;
}

// ---------------- K5: split-bf16 mma.sync GEMM, fused softmax + pooling -----
// grid (8, 192): bx = N-block (128 cols), by = M-block (256 tokens).
// 512 threads, 16 warps 4x4; warp tile 64x32; 2-stage cp.async; 1 sync/stage.
__global__ __launch_bounds__(512, 1) void big_mma_kernel(
    const __nv_bfloat16* __restrict__ xhi, const __nv_bfloat16* __restrict__ xlo,
    const __nv_bfloat16* __restrict__ wth, const __nv_bfloat16* __restrict__ wtl,
    const float* __restrict__ b1, const float* __restrict__ s,
    float* __restrict__ ph) {
    extern __shared__ __align__(16) char smc[];
    float* sexp = (float*)(smc + OFF_ATT);
    float* b1s  = (float*)(smc + OFF_B1);
    float* cols = (float*)(smc + OFF_COL);
    float* sred = (float*)(smc + OFF_RED);
    uint32_t sbase = (uint32_t)__cvta_generic_to_shared(smc);

    int tid = threadIdx.x;
    int wid = tid >> 5, lane = tid & 31;
    int wm = wid >> 2, wn = wid & 3;
    int g = lane >> 2, tg = lane & 3;

    int n0 = blockIdx.x * 128;
    int by = blockIdx.y;
    int branch = by >> 6, w_in = by & 63;
    int batch = w_in >> 1, half = w_in & 1;
    int arow = branch * NB + batch;
    size_t rowbase = (size_t)by * 256;

    // ---- stage loader: K=32 per stage; A 256 rows, B 128 rows ----
    auto load_stage = [&](int st) {
        char* buf = smc + (st & 1) * STAGE_B;
        int k0 = st * 32;
#pragma unroll
        for (int c = tid; c < 1024; c += 512) {
            int r = c >> 2, j = c & 3;
            int off = r * ROW_B + j * 16;
            size_t asrc = (rowbase + r) * DDIM + k0 + j * 8;
            cp16(buf + off, xhi + asrc);
            cp16(buf + PLANE_A + off, xlo + asrc);
        }
        {
            int c = tid;
            if (c < 512) {
                int r = c >> 2, j = c & 3;
                int off = 2 * PLANE_A + r * ROW_B + j * 16;
                size_t bsrc = (size_t)(n0 + r) * DDIM + k0 + j * 8;
                cp16(buf + off, wth + bsrc);
                cp16(buf + PLANE_Bq + off, wtl + bsrc);
            }
        }
    };

    load_stage(0); cp_commit();

    // ---- fused softmax over the full s row (512 entries) ----
    {
        float v = s[(size_t)arow * TLEN + tid];
        sred[tid] = v;
        __syncthreads();
        for (int st = 256; st > 0; st >>= 1) {
            if (tid < st) sred[tid] = fmaxf(sred[tid], sred[tid + st]);
            __syncthreads();
        }
        float mx = sred[0];
        __syncthreads();
        float e = expf(v - mx);
        sred[tid] = e;
        __syncthreads();
        for (int st = 256; st > 0; st >>= 1) {
            if (tid < st) sred[tid] += sred[tid + st];
            __syncthreads();
        }
        float inv = 1.0f / sred[0];
        sexp[tid] = e * inv;
    }
    if (tid < 128) { b1s[tid] = b1[n0 + tid]; cols[tid] = 0.f; }

    float acc[4][4][4];
#pragma unroll
    for (int mi = 0; mi < 4; mi++)
#pragma unroll
        for (int ni = 0; ni < 4; ni++)
#pragma unroll
            for (int j = 0; j < 4; j++) acc[mi][ni][j] = 0.f;

    uint32_t a_l = (uint32_t)((wm * 64 + (lane & 15)) * ROW_B + (lane >> 4) * 16);
    uint32_t b_l = (uint32_t)((wn * 32 + (lane & 7) + ((lane >> 4) << 3)) * ROW_B +
                              ((lane >> 3) & 1) * 16);

    for (int st = 0; st < 32; ++st) {
        cp_wait0();
        __syncthreads();
        if (st + 1 < 32) { load_stage(st + 1); cp_commit(); }
        uint32_t buf = sbase + (uint32_t)(st & 1) * STAGE_B;
#pragma unroll
        for (int ksub = 0; ksub < 2; ++ksub) {
            uint32_t aoff = buf + a_l + (uint32_t)ksub * 32u;
            uint32_t boff = buf + 2u * PLANE_A + b_l + (uint32_t)ksub * 32u;
            uint32_t a[4][4], bh[2][4], bl[2][4];
#pragma unroll
            for (int mi = 0; mi < 4; mi++) ldm4(a[mi], aoff + mi * (16 * ROW_B));
#pragma unroll
            for (int p = 0; p < 2; p++) {
                ldm4(bh[p], boff + p * (16 * ROW_B));
                ldm4(bl[p], boff + PLANE_Bq + p * (16 * ROW_B));
            }
#pragma unroll
            for (int mi = 0; mi < 4; mi++)
#pragma unroll
                for (int ni = 0; ni < 4; ni++) {
                    mma_bf16(acc[mi][ni], a[mi], &bh[ni >> 1][(ni & 1) * 2]);
                    mma_bf16(acc[mi][ni], a[mi], &bl[ni >> 1][(ni & 1) * 2]);
                }
            // lo-plane A reuses the a registers
#pragma unroll
            for (int mi = 0; mi < 4; mi++)
                ldm4(a[mi], aoff + PLANE_A + mi * (16 * ROW_B));
#pragma unroll
            for (int mi = 0; mi < 4; mi++)
#pragma unroll
                for (int ni = 0; ni < 4; ni++)
                    mma_bf16(acc[mi][ni], a[mi], &bh[ni >> 1][(ni & 1) * 2]);
        }
    }

    // ---- epilogue: pooled_col += sum_rows attn[row] * relu(acc + b1[col]) ----
    const float* att_s = sexp + half * 256;
#pragma unroll
    for (int mi = 0; mi < 4; mi++) {
        int rA = wm * 64 + mi * 16 + g;
        float wA = att_s[rA], wB = att_s[rA + 8];
#pragma unroll
        for (int ni = 0; ni < 4; ni++) {
            int c0 = wn * 32 + ni * 8 + tg * 2;
            float bv0 = b1s[c0], bv1 = b1s[c0 + 1];
            float v0 = fmaxf(acc[mi][ni][0] + bv0, 0.f) * wA +
                       fmaxf(acc[mi][ni][2] + bv0, 0.f) * wB;
            float v1 = fmaxf(acc[mi][ni][1] + bv1, 0.f) * wA +
                       fmaxf(acc[mi][ni][3] + bv1, 0.f) * wB;
#pragma unroll
            for (int o = 4; o <= 16; o <<= 1) {
                v0 += __shfl_xor_sync(0xffffffffu, v0, o);
                v1 += __shfl_xor_sync(0xffffffffu, v1, o);
            }
            if (g == 0) {
                atomicAdd(&cols[c0], v0);
                atomicAdd(&cols[c0 + 1], v1);
            }
        }
    }
    __syncthreads();
    if (tid < 128) atomicAdd(&ph[(size_t)arow * DDIM + n0 + tid], cols[tid]);
}

// ---------------- K6: layernorm + relu + last linear -----------------------
__global__ void final_kernel(const float* __restrict__ pooled,
                             const float* __restrict__ ln_g, const float* __restrict__ ln_b,
                             const float* __restrict__ W_last, const float* __restrict__ b_last,
                             float* __restrict__ out) {
    int row = blockIdx.y * NB + blockIdx.x;
    int tid = threadIdx.x;
    __shared__ float act[DDIM];
    __shared__ float red[128];

    float vals[8];
    float lsum = 0.f;
#pragma unroll
    for (int i = 0; i < 8; i++) {
        vals[i] = pooled[(size_t)row * DDIM + tid + i * 128];
        lsum += vals[i];
    }
    red[tid] = lsum;
    __syncthreads();
    for (int s = 64; s > 0; s >>= 1) {
        if (tid < s) red[tid] += red[tid + s];
        __syncthreads();
    }
    float mu = red[0] * (1.0f / DDIM);
    __syncthreads();
    float lsq = 0.f;
#pragma unroll
    for (int i = 0; i < 8; i++) {
        float d = vals[i] - mu;
        lsq += d * d;
    }
    red[tid] = lsq;
    __syncthreads();
    for (int s = 64; s > 0; s >>= 1) {
        if (tid < s) red[tid] += red[tid + s];
        __syncthreads();
    }
    float var = red[0] * (1.0f / DDIM);
    float vv = var + 1e-12f;
    float inv = rsqrtf(vv);
    inv = inv * (1.5f - 0.5f * vv * inv * inv);  // Newton refine
    __syncthreads();
#pragma unroll
    for (int i = 0; i < 8; i++) {
        int d = tid + i * 128;
        float nvv = (vals[i] - mu) * inv * ln_g[d] + ln_b[d];
        act[d] = fmaxf(nvv, 0.f);
    }
    __syncthreads();
    if (tid < CDIM) {
        float accv = b_last[tid];
        for (int d = 0; d < DDIM; d++) accv += act[d] * W_last[(size_t)d * CDIM + tid];
        out[(size_t)row * CDIM + tid] = accv;
    }
}

// ---------------- launch ----------------------------------------------------
extern "C" void kernel_launch(void* const* d_in, const int* in_sizes, int n_in,
                              void* d_out, int out_size) {
    const float* x0 = (const float*)d_in[0];
    const float* x1 = (const float*)d_in[1];
    const float* x2 = (const float*)d_in[2];
    const int* m0 = (const int*)d_in[3];
    const int* m1 = (const int*)d_in[4];
    const int* m2 = (const int*)d_in[5];
    const float* W_attn = (const float*)d_in[6];
    const float* b_attn = (const float*)d_in[7];
    const float* W1 = (const float*)d_in[8];
    const float* b1 = (const float*)d_in[9];
    const float* W2 = (const float*)d_in[10];
    const float* b2 = (const float*)d_in[11];
    const float* ln_g = (const float*)d_in[12];
    const float* ln_b = (const float*)d_in[13];
    const float* W_last = (const float*)d_in[14];
    const float* b_last = (const float*)d_in[15];
    float* out = (float*)d_out;

    float *p_xsum, *p_nv, *p_u, *p_ub, *p_v, *p_s, *p_ph, *p_pooled;
    __nv_bfloat16 *p_xhi, *p_xlo, *p_wth, *p_wtl;
    cudaGetSymbolAddress((void**)&p_xsum, g_xsum);
    cudaGetSymbolAddress((void**)&p_nv, g_nv);
    cudaGetSymbolAddress((void**)&p_u, g_u);
    cudaGetSymbolAddress((void**)&p_ub, g_ub);
    cudaGetSymbolAddress((void**)&p_v, g_v);
    cudaGetSymbolAddress((void**)&p_s, g_s);
    cudaGetSymbolAddress((void**)&p_ph, g_ph);
    cudaGetSymbolAddress((void**)&p_pooled, g_pooled);
    cudaGetSymbolAddress((void**)&p_xhi, g_xhi);
    cudaGetSymbolAddress((void**)&p_xlo, g_xlo);
    cudaGetSymbolAddress((void**)&p_wth, g_w1t_hi);
    cudaGetSymbolAddress((void**)&p_wtl, g_w1t_lo);

    cudaFuncSetAttribute(big_mma_kernel, cudaFuncAttributeMaxDynamicSharedMemorySize,
                         SMEM_REQ);

    combo_kernel<<<1408, 256>>>(W1, p_wth, p_wtl, p_ph, p_xsum, p_u, p_v,
                                p_pooled, p_nv, p_ub);
    convsum_kernel<<<dim3(8, NB, 3), 256>>>(x0, x1, x2, m0, m1, m2,
                                            p_xhi, p_xlo, p_xsum, p_nv);
    gemm96_kernel<0><<<dim3(16, 3, 4), 256>>>(p_xsum, W_attn, p_u, b_attn, p_nv, p_ub);
    gemm96_kernel<1><<<dim3(16, 3, 4), 256>>>(p_u, W_attn, p_v, nullptr, nullptr, nullptr);
    s_kernel<<<dim3(64, NB, 3), 256>>>(x0, x1, x2, m0, m1, m2, p_v, p_ub, p_s);
    big_mma_kernel<<<dim3(8, 192), 512, SMEM_REQ>>>(p_xhi, p_xlo, p_wth, p_wtl,
                                                    b1, p_s, p_ph);
    gemm96_kernel<2><<<dim3(16, 3, 4), 256>>>(p_ph, W2, p_pooled, b2, nullptr, nullptr);
    final_kernel<<<dim3(NB, 3), 128>>>(p_pooled, ln_g, ln_b, W_last, b_last, out);
}

// round 7
// speedup vs baseline: 3.2477x; 1.4961x over previous
#include <cuda_runtime.h>
#include <cuda_bf16.h>
#include <cstdint>
#include <math.h>

// Problem constants
#define NB   32
#define TLEN 512
#define DDIM 1024
#define CDIM 120
#define NROWS 96            // 3 branches * 32 batches
#define INV_SCALE 0.015625f // 1 / (2*sqrt(1024)) = 1/64
#define TOTROWS 49152       // 3 * 32 * 512 tokens

#define NEG_INF __int_as_float(0xff800000)

// ---------------- scratch (device globals; no allocation allowed) ----------
__device__ float g_xsum[NROWS * DDIM];
__device__ float g_nv[NROWS];
__device__ float g_u[NROWS * DDIM];
__device__ float g_ub[NROWS];
__device__ float g_v[NROWS * DDIM];
__device__ float g_s[NROWS * TLEN];     // compacted scores
__device__ float g_ph[NROWS * DDIM];
__device__ float g_pooled[NROWS * DDIM];
__device__ int   g_rank[NROWS * TLEN];  // compact rank per token, -1 if masked
__device__ int   g_V[NROWS];            // valid count per row
// split-bf16 operands (COMPACTED rows) for the tensor-core GEMM
__device__ __nv_bfloat16 g_xhi[(size_t)TOTROWS * DDIM];
__device__ __nv_bfloat16 g_xlo[(size_t)TOTROWS * DDIM];
__device__ __nv_bfloat16 g_w1t_hi[DDIM * DDIM];
__device__ __nv_bfloat16 g_w1t_lo[DDIM * DDIM];

// =================== helpers =================================================
__device__ __forceinline__ void cp16(void* d, const void* s) {
    asm volatile("cp.async.cg.shared.global [%0], [%1], 16;"
                 :: "l"(__cvta_generic_to_shared(d)), "l"(s));
}
__device__ __forceinline__ void cp_commit() {
    asm volatile("cp.async.commit_group;" ::: "memory");
}
__device__ __forceinline__ void cp_wait1() {
    asm volatile("cp.async.wait_group 1;" ::: "memory");
}
__device__ __forceinline__ void cp_wait0() {
    asm volatile("cp.async.wait_group 0;" ::: "memory");
}
__device__ __forceinline__ void mma_bf16(float* d, const uint32_t* a, const uint32_t* b) {
    asm volatile(
        "mma.sync.aligned.m16n8k16.row.col.f32.bf16.bf16.f32 "
        "{%0,%1,%2,%3}, {%4,%5,%6,%7}, {%8,%9}, {%0,%1,%2,%3};"
        : "+f"(d[0]), "+f"(d[1]), "+f"(d[2]), "+f"(d[3])
        : "r"(a[0]), "r"(a[1]), "r"(a[2]), "r"(a[3]), "r"(b[0]), "r"(b[1]));
}
__device__ __forceinline__ void ldm4(uint32_t* r, uint32_t saddr) {
    asm volatile("ldmatrix.sync.aligned.m8n8.x4.shared.b16 {%0,%1,%2,%3}, [%4];"
                 : "=r"(r[0]), "=r"(r[1]), "=r"(r[2]), "=r"(r[3]) : "r"(saddr));
}

// SMEM layout of big kernel: 2 stages x 40960B (M=128 x N=128 x K=32)
// stage: Ahi[128][40] | Alo | Bhi[128][40] | Blo  (row stride 40 halfs = 80B)
#define STAGE_B   40960
#define PLANE_B   10240
#define ROW_B     80
#define OFF_SEXP  81920   // 512 floats: softmax of compacted s
#define OFF_B1    83968   // 128 floats
#define OFF_COL   84480   // 128 floats
#define OFF_RED   84992   // 256 floats
#define SMEM_REQ  86016

// ---------------- K0: zero scratch + conv W1 (fused) ------------------------
__global__ void combo_kernel(const float* __restrict__ W1,
                             __nv_bfloat16* __restrict__ th,
                             __nv_bfloat16* __restrict__ tl,
                             float* __restrict__ ph, float* __restrict__ xsum,
                             float* __restrict__ u, float* __restrict__ v,
                             float* __restrict__ pooled, float* __restrict__ ub) {
    int bx = blockIdx.x;
    if (bx < 384) {
        int i = bx * 256 + threadIdx.x;   // covers 98304 = NROWS*DDIM
        ph[i] = 0.f; xsum[i] = 0.f; u[i] = 0.f; v[i] = 0.f; pooled[i] = 0.f;
        if (i < NROWS) ub[i] = 0.f;
    } else {
        __shared__ float tile[32][33];
        int b = bx - 384;
        int n0 = (b & 31) * 32, k0 = (b >> 5) * 32;
        int tx = threadIdx.x & 31, ty = threadIdx.x >> 5;
        for (int r = ty; r < 32; r += 8)
            tile[r][tx] = W1[(size_t)(k0 + r) * DDIM + n0 + tx];
        __syncthreads();
        for (int r = ty; r < 32; r += 8) {
            float w = tile[tx][r];  // = W1[k0+tx][n0+r]
            __nv_bfloat16 h = __float2bfloat16(w);
            __nv_bfloat16 l = __float2bfloat16(w - __bfloat162float(h));
            size_t o = (size_t)(n0 + r) * DDIM + k0 + tx;
            th[o] = h; tl[o] = l;
        }
    }
}

// ---------------- K0b: mask scan -> rank/V/nv --------------------------------
__global__ void mask_scan_kernel(const int* __restrict__ m0, const int* __restrict__ m1,
                                 const int* __restrict__ m2,
                                 int* __restrict__ rank, int* __restrict__ V,
                                 float* __restrict__ nv) {
    int b = blockIdx.x, br = blockIdx.y;
    const int* M = ((br == 0) ? m0 : (br == 1) ? m1 : m2) + (size_t)b * TLEN;
    int row = br * NB + b;
    int tid = threadIdx.x;  // 512
    __shared__ int ps[TLEN];
    int valid = (M[tid] == 0) ? 1 : 0;
    ps[tid] = valid;
    __syncthreads();
    for (int off = 1; off < TLEN; off <<= 1) {
        int vv = (tid >= off) ? ps[tid - off] : 0;
        __syncthreads();
        ps[tid] += vv;
        __syncthreads();
    }
    rank[row * TLEN + tid] = valid ? (ps[tid] - 1) : -1;
    if (tid == TLEN - 1) {
        V[row] = ps[TLEN - 1];
        nv[row] = (float)ps[TLEN - 1];
    }
}

// ---------------- fused: valid x -> compacted bf16 hi/lo + masked sum -------
__global__ void convsum_kernel(const float* __restrict__ x0, const float* __restrict__ x1,
                               const float* __restrict__ x2,
                               const int* __restrict__ rank,
                               __nv_bfloat16* __restrict__ xhi,
                               __nv_bfloat16* __restrict__ xlo,
                               float* __restrict__ xsum) {
    int ch = blockIdx.x, b = blockIdx.y, br = blockIdx.z;
    const float* X = (br == 0) ? x0 : (br == 1) ? x1 : x2;
    int row = br * NB + b;
    __shared__ int smr[64];
    int tid = threadIdx.x;
    if (tid < 64) smr[tid] = rank[row * TLEN + ch * 64 + tid];
    __syncthreads();

    const float* xp = X + ((size_t)b * TLEN + ch * 64) * DDIM + tid * 4;
    size_t cbase = (size_t)row * TLEN;   // compact row base
    float ax = 0.f, ay = 0.f, az = 0.f, aw = 0.f;
    for (int t = 0; t < 64; t++) {
        int rk = smr[t];
        if (rk >= 0) {
            float4 v = *(const float4*)(xp + (size_t)t * DDIM);
            __nv_bfloat16 h0 = __float2bfloat16(v.x);
            __nv_bfloat16 h1 = __float2bfloat16(v.y);
            __nv_bfloat16 h2 = __float2bfloat16(v.z);
            __nv_bfloat16 h3 = __float2bfloat16(v.w);
            __nv_bfloat16 l0 = __float2bfloat16(v.x - __bfloat162float(h0));
            __nv_bfloat16 l1 = __float2bfloat16(v.y - __bfloat162float(h1));
            __nv_bfloat16 l2 = __float2bfloat16(v.z - __bfloat162float(h2));
            __nv_bfloat16 l3 = __float2bfloat16(v.w - __bfloat162float(h3));
            size_t o = (cbase + rk) * DDIM + tid * 4;
            __nv_bfloat162* ph2 = (__nv_bfloat162*)(xhi + o);
            __nv_bfloat162* pl2 = (__nv_bfloat162*)(xlo + o);
            ph2[0] = __nv_bfloat162(h0, h1); ph2[1] = __nv_bfloat162(h2, h3);
            pl2[0] = __nv_bfloat162(l0, l1); pl2[1] = __nv_bfloat162(l2, l3);
            ax += v.x; ay += v.y; az += v.z; aw += v.w;
        }
    }
    float* xr = xsum + (size_t)row * DDIM + tid * 4;
    atomicAdd(xr + 0, ax);
    atomicAdd(xr + 1, ay);
    atomicAdd(xr + 2, az);
    atomicAdd(xr + 3, aw);
}

// ---------------- small GEMM, K-split x4: (96 x 1024) @ (1024 x 1024) -------
template <int MODE>
__global__ void gemm96_kernel(const float* __restrict__ A, const float* __restrict__ B,
                              float* __restrict__ C, const float* __restrict__ bias,
                              const float* __restrict__ nv, float* __restrict__ ub) {
    const int BK = 32;
    __shared__ float As[32][BK + 1];
    __shared__ float Bs[BK][64 + 1];
    int m0 = blockIdx.y * 32;
    int n0 = blockIdx.x * 64;
    int ks = blockIdx.z * 256;
    int tid = threadIdx.x;
    int tx = tid & 15, ty = tid >> 4;
    int lane = tid & 31;

    float acc[2][4] = {{0.f, 0.f, 0.f, 0.f}, {0.f, 0.f, 0.f, 0.f}};

    for (int k0 = ks; k0 < ks + 256; k0 += BK) {
#pragma unroll
        for (int i = 0; i < 4; i++) {
            int l = tid + i * 256;
            int r = l >> 5, k = l & 31;
            As[r][k] = A[(size_t)(m0 + r) * DDIM + k0 + k];
        }
        if (MODE == 1) {
#pragma unroll
            for (int i = 0; i < 8; i++) {
                int l = tid + i * 256;
                int kk = l & 31, n = l >> 5;
                Bs[kk][n] = B[(size_t)(n0 + n) * DDIM + k0 + kk];
            }
        } else {
#pragma unroll
            for (int i = 0; i < 8; i++) {
                int l = tid + i * 256;
                int kk = l >> 6, n = l & 63;
                Bs[kk][n] = B[(size_t)(k0 + kk) * DDIM + n0 + n];
            }
        }
        __syncthreads();
#pragma unroll
        for (int kk = 0; kk < BK; kk++) {
            float a0 = As[ty * 2 + 0][kk];
            float a1 = As[ty * 2 + 1][kk];
#pragma unroll
            for (int j = 0; j < 4; j++) {
                float bv = Bs[kk][tx * 4 + j];
                acc[0][j] += a0 * bv;
                acc[1][j] += a1 * bv;
            }
        }
        __syncthreads();
    }

    float vv[2][4];
#pragma unroll
    for (int i = 0; i < 2; i++) {
        int r = m0 + ty * 2 + i;
#pragma unroll
        for (int j = 0; j < 4; j++) {
            int c = n0 + tx * 4 + j;
            float v = acc[i][j];
            if (MODE == 0 && blockIdx.z == 0) v += nv[r] * bias[c];
            if (MODE == 2 && blockIdx.z == 0) v += bias[c];
            vv[i][j] = v;
            atomicAdd(&C[(size_t)r * DDIM + c], v);
        }
    }
    if (MODE == 0) {
        float u0 = 0.f, u1 = 0.f;
#pragma unroll
        for (int j = 0; j < 4; j++) {
            float ba = bias[n0 + tx * 4 + j];
            u0 += vv[0][j] * ba;
            u1 += vv[1][j] * ba;
        }
#pragma unroll
        for (int o = 8; o > 0; o >>= 1) {
            u0 += __shfl_xor_sync(0xffffffffu, u0, o);
            u1 += __shfl_xor_sync(0xffffffffu, u1, o);
        }
        if ((lane & 15) == 0) {
            atomicAdd(&ub[m0 + ty * 2 + 0], u0);
            atomicAdd(&ub[m0 + ty * 2 + 1], u1);
        }
    }
}

// ---------------- K3: compacted s[row][rank] = (x_t . v + ub)/SCALE ---------
__global__ void s_kernel(const float* __restrict__ x0, const float* __restrict__ x1,
                         const float* __restrict__ x2,
                         const int* __restrict__ rank,
                         const float* __restrict__ v, const float* __restrict__ ub,
                         float* __restrict__ s) {
    int br = blockIdx.z, b = blockIdx.y;
    int w = threadIdx.x >> 5, lane = threadIdx.x & 31;
    int t = blockIdx.x * 8 + w;
    const float* X = (br == 0) ? x0 : (br == 1) ? x1 : x2;
    int row = br * NB + b;
    int rk = rank[row * TLEN + t];
    if (rk < 0) return;
    const float* xr = X + ((size_t)b * TLEN + t) * DDIM;
    const float* vr = v + (size_t)row * DDIM;
    float acc = 0.f;
#pragma unroll
    for (int i = 0; i < 8; i++) {
        int d = lane * 4 + i * 128;
        float4 xv = *(const float4*)&xr[d];
        float4 vv = *(const float4*)&vr[d];
        acc += xv.x * vv.x + xv.y * vv.y + xv.z * vv.z + xv.w * vv.w;
    }
#pragma unroll
    for (int o = 16; o > 0; o >>= 1) acc += __shfl_xor_sync(0xffffffffu, acc, o);
    if (lane == 0) s[row * TLEN + rk] = (acc + ub[row]) * INV_SCALE;
}

// ---------------- K5: split-bf16 mma.sync GEMM over COMPACTED rows ----------
// grid (8, 384): bx = N-block (128 cols); by: arow = by>>2, tile = by&3.
// Tiles beyond V[arow] exit immediately (~38% of tiles on average).
// 256 threads, 8 warps 2x4; warp tile 64x32; fused softmax over compact s.
__global__ __launch_bounds__(256, 2) void big_mma_kernel(
    const __nv_bfloat16* __restrict__ xhi, const __nv_bfloat16* __restrict__ xlo,
    const __nv_bfloat16* __restrict__ wth, const __nv_bfloat16* __restrict__ wtl,
    const float* __restrict__ b1, const float* __restrict__ s,
    const int* __restrict__ Varr, float* __restrict__ ph) {
    extern __shared__ __align__(16) char smc[];
    float* sexp = (float*)(smc + OFF_SEXP);
    float* b1s  = (float*)(smc + OFF_B1);
    float* cols = (float*)(smc + OFF_COL);
    float* sred = (float*)(smc + OFF_RED);
    uint32_t sbase = (uint32_t)__cvta_generic_to_shared(smc);

    int by = blockIdx.y;
    int arow = by >> 2, tile = by & 3;
    int V = Varr[arow];
    if (tile * 128 >= V) return;

    int tid = threadIdx.x;
    int wid = tid >> 5, lane = tid & 31;
    int wm = wid >> 2, wn = wid & 3;
    int g = lane >> 2, tg = lane & 3;
    int n0 = blockIdx.x * 128;
    size_t rowbase = (size_t)arow * TLEN + tile * 128;

    // ---- stage loader: K=32 per stage; A 128 compact rows, B 128 cols ----
    auto load_stage = [&](int st) {
        char* buf = smc + (st & 1) * STAGE_B;
        int k0 = st * 32;
#pragma unroll
        for (int c = tid; c < 512; c += 256) {
            int r = c >> 2, j = c & 3;
            int off = r * ROW_B + j * 16;
            size_t asrc = (rowbase + r) * DDIM + k0 + j * 8;
            size_t bsrc = (size_t)(n0 + r) * DDIM + k0 + j * 8;
            cp16(buf + off, xhi + asrc);
            cp16(buf + PLANE_B + off, xlo + asrc);
            cp16(buf + 2 * PLANE_B + off, wth + bsrc);
            cp16(buf + 3 * PLANE_B + off, wtl + bsrc);
        }
    };

    load_stage(0); cp_commit();

    // ---- fused softmax over compact s (length V, buffer 512) ----
    {
        float v0 = (tid < V) ? s[arow * TLEN + tid] : NEG_INF;
        float v1 = (tid + 256 < V) ? s[arow * TLEN + tid + 256] : NEG_INF;
        sred[tid] = fmaxf(v0, v1);
        __syncthreads();
        for (int st = 128; st > 0; st >>= 1) {
            if (tid < st) sred[tid] = fmaxf(sred[tid], sred[tid + st]);
            __syncthreads();
        }
        float mx = sred[0];
        __syncthreads();
        float e0 = (tid < V) ? expf(v0 - mx) : 0.f;
        float e1 = (tid + 256 < V) ? expf(v1 - mx) : 0.f;
        sred[tid] = e0 + e1;
        __syncthreads();
        for (int st = 128; st > 0; st >>= 1) {
            if (tid < st) sred[tid] += sred[tid + st];
            __syncthreads();
        }
        float inv = 1.0f / sred[0];
        sexp[tid] = e0 * inv;
        sexp[tid + 256] = e1 * inv;
    }
    if (tid < 128) { b1s[tid] = b1[n0 + tid]; cols[tid] = 0.f; }

    float acc[4][4][4];
#pragma unroll
    for (int mi = 0; mi < 4; mi++)
#pragma unroll
        for (int ni = 0; ni < 4; ni++)
#pragma unroll
            for (int j = 0; j < 4; j++) acc[mi][ni][j] = 0.f;

    uint32_t a_l = (uint32_t)((wm * 64 + (lane & 15)) * ROW_B + (lane >> 4) * 16);
    uint32_t b_l = (uint32_t)((wn * 32 + (lane & 7) + ((lane >> 4) << 3)) * ROW_B +
                              ((lane >> 3) & 1) * 16);

    for (int st = 0; st < 32; ++st) {
        if (st + 1 < 32) { load_stage(st + 1); cp_commit(); cp_wait1(); }
        else            { cp_wait0(); }
        __syncthreads();
        uint32_t buf = sbase + (uint32_t)(st & 1) * STAGE_B;
#pragma unroll
        for (int ksub = 0; ksub < 2; ++ksub) {
            uint32_t aoff = buf + a_l + (uint32_t)ksub * 32u;
            uint32_t boff = buf + 2u * PLANE_B + b_l + (uint32_t)ksub * 32u;
            uint32_t a[4][4], bh[2][4], bl[2][4];
#pragma unroll
            for (int mi = 0; mi < 4; mi++) ldm4(a[mi], aoff + mi * (16 * ROW_B));
#pragma unroll
            for (int p = 0; p < 2; p++) {
                ldm4(bh[p], boff + p * (16 * ROW_B));
                ldm4(bl[p], boff + PLANE_B + p * (16 * ROW_B));
            }
#pragma unroll
            for (int mi = 0; mi < 4; mi++)
#pragma unroll
                for (int ni = 0; ni < 4; ni++) {
                    mma_bf16(acc[mi][ni], a[mi], &bh[ni >> 1][(ni & 1) * 2]);
                    mma_bf16(acc[mi][ni], a[mi], &bl[ni >> 1][(ni & 1) * 2]);
                }
            // lo-plane A reuses the a registers
#pragma unroll
            for (int mi = 0; mi < 4; mi++)
                ldm4(a[mi], aoff + PLANE_B + mi * (16 * ROW_B));
#pragma unroll
            for (int mi = 0; mi < 4; mi++)
#pragma unroll
                for (int ni = 0; ni < 4; ni++)
                    mma_bf16(acc[mi][ni], a[mi], &bh[ni >> 1][(ni & 1) * 2]);
        }
        __syncthreads();
    }

    // ---- epilogue: pooled_col += sum_rows attn[row] * relu(acc + b1[col]) ----
    const float* att_s = sexp + tile * 128;
#pragma unroll
    for (int mi = 0; mi < 4; mi++) {
        int rA = wm * 64 + mi * 16 + g;
        float wA = att_s[rA], wB = att_s[rA + 8];
#pragma unroll
        for (int ni = 0; ni < 4; ni++) {
            int c0 = wn * 32 + ni * 8 + tg * 2;
            float bv0 = b1s[c0], bv1 = b1s[c0 + 1];
            float v0 = fmaxf(acc[mi][ni][0] + bv0, 0.f) * wA +
                       fmaxf(acc[mi][ni][2] + bv0, 0.f) * wB;
            float v1 = fmaxf(acc[mi][ni][1] + bv1, 0.f) * wA +
                       fmaxf(acc[mi][ni][3] + bv1, 0.f) * wB;
#pragma unroll
            for (int o = 4; o <= 16; o <<= 1) {
                v0 += __shfl_xor_sync(0xffffffffu, v0, o);
                v1 += __shfl_xor_sync(0xffffffffu, v1, o);
            }
            if (g == 0) {
                atomicAdd(&cols[c0], v0);
                atomicAdd(&cols[c0 + 1], v1);
            }
        }
    }
    __syncthreads();
    if (tid < 128) atomicAdd(&ph[(size_t)arow * DDIM + n0 + tid], cols[tid]);
}

// ---------------- K6: layernorm + relu + last linear -----------------------
__global__ void final_kernel(const float* __restrict__ pooled,
                             const float* __restrict__ ln_g, const float* __restrict__ ln_b,
                             const float* __restrict__ W_last, const float* __restrict__ b_last,
                             float* __restrict__ out) {
    int row = blockIdx.y * NB + blockIdx.x;
    int tid = threadIdx.x;
    __shared__ float act[DDIM];
    __shared__ float red[128];

    float vals[8];
    float lsum = 0.f;
#pragma unroll
    for (int i = 0; i < 8; i++) {
        vals[i] = pooled[(size_t)row * DDIM + tid + i * 128];
        lsum += vals[i];
    }
    red[tid] = lsum;
    __syncthreads();
    for (int s = 64; s > 0; s >>= 1) {
        if (tid < s) red[tid] += red[tid + s];
        __syncthreads();
    }
    float mu = red[0] * (1.0f / DDIM);
    __syncthreads();
    float lsq = 0.f;
#pragma unroll
    for (int i = 0; i < 8; i++) {
        float d = vals[i] - mu;
        lsq += d * d;
    }
    red[tid] = lsq;
    __syncthreads();
    for (int s = 64; s > 0; s >>= 1) {
        if (tid < s) red[tid] += red[tid + s];
        __syncthreads();
    }
    float var = red[0] * (1.0f / DDIM);
    float vv = var + 1e-12f;
    float inv = rsqrtf(vv);
    inv = inv * (1.5f - 0.5f * vv * inv * inv);  // Newton refine
    __syncthreads();
#pragma unroll
    for (int i = 0; i < 8; i++) {
        int d = tid + i * 128;
        float nvv = (vals[i] - mu) * inv * ln_g[d] + ln_b[d];
        act[d] = fmaxf(nvv, 0.f);
    }
    __syncthreads();
    if (tid < CDIM) {
        float accv = b_last[tid];
        for (int d = 0; d < DDIM; d++) accv += act[d] * W_last[(size_t)d * CDIM + tid];
        out[(size_t)row * CDIM + tid] = accv;
    }
}

// ---------------- launch ----------------------------------------------------
extern "C" void kernel_launch(void* const* d_in, const int* in_sizes, int n_in,
                              void* d_out, int out_size) {
    const float* x0 = (const float*)d_in[0];
    const float* x1 = (const float*)d_in[1];
    const float* x2 = (const float*)d_in[2];
    const int* m0 = (const int*)d_in[3];
    const int* m1 = (const int*)d_in[4];
    const int* m2 = (const int*)d_in[5];
    const float* W_attn = (const float*)d_in[6];
    const float* b_attn = (const float*)d_in[7];
    const float* W1 = (const float*)d_in[8];
    const float* b1 = (const float*)d_in[9];
    const float* W2 = (const float*)d_in[10];
    const float* b2 = (const float*)d_in[11];
    const float* ln_g = (const float*)d_in[12];
    const float* ln_b = (const float*)d_in[13];
    const float* W_last = (const float*)d_in[14];
    const float* b_last = (const float*)d_in[15];
    float* out = (float*)d_out;

    float *p_xsum, *p_nv, *p_u, *p_ub, *p_v, *p_s, *p_ph, *p_pooled;
    int *p_rank, *p_V;
    __nv_bfloat16 *p_xhi, *p_xlo, *p_wth, *p_wtl;
    cudaGetSymbolAddress((void**)&p_xsum, g_xsum);
    cudaGetSymbolAddress((void**)&p_nv, g_nv);
    cudaGetSymbolAddress((void**)&p_u, g_u);
    cudaGetSymbolAddress((void**)&p_ub, g_ub);
    cudaGetSymbolAddress((void**)&p_v, g_v);
    cudaGetSymbolAddress((void**)&p_s, g_s);
    cudaGetSymbolAddress((void**)&p_ph, g_ph);
    cudaGetSymbolAddress((void**)&p_pooled, g_pooled);
    cudaGetSymbolAddress((void**)&p_rank, g_rank);
    cudaGetSymbolAddress((void**)&p_V, g_V);
    cudaGetSymbolAddress((void**)&p_xhi, g_xhi);
    cudaGetSymbolAddress((void**)&p_xlo, g_xlo);
    cudaGetSymbolAddress((void**)&p_wth, g_w1t_hi);
    cudaGetSymbolAddress((void**)&p_wtl, g_w1t_lo);

    cudaFuncSetAttribute(big_mma_kernel, cudaFuncAttributeMaxDynamicSharedMemorySize,
                         SMEM_REQ);

    combo_kernel<<<1408, 256>>>(W1, p_wth, p_wtl, p_ph, p_xsum, p_u, p_v,
                                p_pooled, p_ub);
    mask_scan_kernel<<<dim3(NB, 3), 512>>>(m0, m1, m2, p_rank, p_V, p_nv);
    convsum_kernel<<<dim3(8, NB, 3), 256>>>(x0, x1, x2, p_rank,
                                            p_xhi, p_xlo, p_xsum);
    gemm96_kernel<0><<<dim3(16, 3, 4), 256>>>(p_xsum, W_attn, p_u, b_attn, p_nv, p_ub);
    gemm96_kernel<1><<<dim3(16, 3, 4), 256>>>(p_u, W_attn, p_v, nullptr, nullptr, nullptr);
    s_kernel<<<dim3(64, NB, 3), 256>>>(x0, x1, x2, p_rank, p_v, p_ub, p_s);
    big_mma_kernel<<<dim3(8, 384), 256, SMEM_REQ>>>(p_xhi, p_xlo, p_wth, p_wtl,
                                                    b1, p_s, p_V, p_ph);
    gemm96_kernel<2><<<dim3(16, 3, 4), 256>>>(p_ph, W2, p_pooled, b2, nullptr, nullptr);
    final_kernel<<<dim3(NB, 3), 128>>>(p_pooled, ln_g, ln_b, W_last, b_last, out);
}